// round 11
// baseline (speedup 1.0000x reference)
#include <cuda_runtime.h>
#include <cuda_fp16.h>
#include <math.h>
#include <stdint.h>

#define B_    2
#define H_    8
#define S_    4096
#define D_    64
#define DM_   512
#define ROWS_ (B_*S_)   // 8192

// ---- scratch (static __device__ arrays; no allocation allowed) ----
__device__ __half g_x [ROWS_*DM_];
__device__ __half g_wq[DM_*DM_];
__device__ __half g_wk[DM_*DM_];
__device__ __half g_wv[DM_*DM_];
__device__ __half g_wo[DM_*DM_];
__device__ __half g_q [B_*H_*S_*D_];   // [B,H,S,D] (Q pre-scaled 1/8*log2e)
__device__ __half g_k [B_*H_*S_*D_];   // [B,H,S,D]
__device__ __half g_vT[B_*H_*D_*S_];   // [B,H,D,S] (transposed)
__device__ __half g_att[ROWS_*DM_];    // attention out, [B,S,H*D]
__device__ float2 g_cs[S_*32];         // (cos, sin) per (s, d2)

__device__ __forceinline__ void cp16h(__half* s, const __half* g) {
    uint32_t sa = (uint32_t)__cvta_generic_to_shared(s);
    asm volatile("cp.async.cg.shared.global [%0], [%1], 16;\n" :: "r"(sa), "l"(g));
}

__device__ __forceinline__ void mma_f16(
    float& c0, float& c1, float& c2, float& c3,
    uint32_t a0, uint32_t a1, uint32_t a2, uint32_t a3,
    uint32_t b0, uint32_t b1)
{
    asm volatile(
        "mma.sync.aligned.m16n8k16.row.col.f32.f16.f16.f32 "
        "{%0,%1,%2,%3}, {%4,%5,%6,%7}, {%8,%9}, {%0,%1,%2,%3};"
        : "+f"(c0), "+f"(c1), "+f"(c2), "+f"(c3)
        : "r"(a0), "r"(a1), "r"(a2), "r"(a3), "r"(b0), "r"(b1));
}

__device__ __forceinline__ void ldsm_x4(
    uint32_t& r0, uint32_t& r1, uint32_t& r2, uint32_t& r3, uint32_t addr)
{
    asm volatile(
        "ldmatrix.sync.aligned.m8n8.x4.shared.b16 {%0,%1,%2,%3}, [%4];"
        : "=r"(r0), "=r"(r1), "=r"(r2), "=r"(r3) : "r"(addr));
}

__device__ __forceinline__ void stsm_x4(
    uint32_t addr, uint32_t r0, uint32_t r1, uint32_t r2, uint32_t r3)
{
    asm volatile(
        "stmatrix.sync.aligned.m8n8.x4.shared.b16 [%0], {%1,%2,%3,%4};"
        :: "r"(addr), "r"(r0), "r"(r1), "r"(r2), "r"(r3) : "memory");
}

__device__ __forceinline__ uint32_t pack2(float a, float b) {
    __half2 h = __floats2half2_rn(a, b);
    return *reinterpret_cast<uint32_t*>(&h);
}

__device__ __forceinline__ uint32_t h2ex2(uint32_t x) {
    uint32_t y;
    asm("ex2.approx.f16x2 %0, %1;" : "=r"(y) : "r"(x));
    return y;
}

// ============================================================================
// One fused prep kernel: fp16-round x & weights + cos/sin table.
// ============================================================================
#define NW4 (DM_*DM_/4)
__global__ __launch_bounds__(256) void prep_kernel(
    const float* __restrict__ x,
    const float* __restrict__ wq, const float* __restrict__ wk,
    const float* __restrict__ wv, const float* __restrict__ wo)
{
    int bx = blockIdx.x;
    if (bx < 4096) {
        int i = bx*256 + threadIdx.x;
        float4 v = ((const float4*)x)[i];
        ((__half2*)g_x)[i*2]   = __floats2half2_rn(v.x, v.y);
        ((__half2*)g_x)[i*2+1] = __floats2half2_rn(v.z, v.w);
    } else if (bx < 5120) {
        int idx = (bx - 4096)*256 + threadIdx.x;
        int seg = idx >> 16;
        int i   = idx & (NW4 - 1);
        const float* src = seg == 0 ? wq : seg == 1 ? wk : seg == 2 ? wv : wo;
        __half* dst      = seg == 0 ? g_wq : seg == 1 ? g_wk : seg == 2 ? g_wv : g_wo;
        float4 v = ((const float4*)src)[i];
        ((__half2*)dst)[i*2]   = __floats2half2_rn(v.x, v.y);
        ((__half2*)dst)[i*2+1] = __floats2half2_rn(v.z, v.w);
    } else {
        int id = (bx - 5120)*256 + threadIdx.x;
        int d2 = id & 31, s = id >> 5;
        double invf = exp2(-(double)d2 * (13.287712379549449 / 32.0));
        double ph   = (double)s * invf;
        double n    = rint(ph * 0.15915494309189535);
        float  r    = (float)(ph - 6.283185307179586 * n);
        float sn, cs;
        sincosf(r, &sn, &cs);
        g_cs[id] = make_float2(cs, sn);
    }
}

// ============================================================================
// Fused QKV GEMM + bias + RoPE + transpose; fp16 in/out; ldmatrix fragments.
// Q scaled by (1/8)*log2(e) so attention softmax can use ex2 directly.
// ============================================================================
#define GH 40   // halves; rows 80B -> LDSM phases all distinct mod 128

__global__ __launch_bounds__(256, 2) void qkv_rope_kernel(
    const float* __restrict__ bq, const float* __restrict__ bk,
    const float* __restrict__ bv)
{
    __shared__ __align__(16) __half As[2][128*GH];
    __shared__ __align__(16) __half Bs[2][128*GH];

    const int tid  = threadIdx.x;
    const int w    = tid >> 5;
    const int lane = tid & 31;
    const int g    = lane >> 2;
    const int t    = lane & 3;
    const int wm   = w >> 1;
    const int wn   = w & 1;
    const int bm   = blockIdx.y * 128;
    const int kind = blockIdx.x >> 2;
    const int bn   = (blockIdx.x & 3) * 128;
    const int K    = DM_;

    const __half* Wbase = kind == 0 ? g_wq : kind == 1 ? g_wk : g_wv;
    const float*  bias  = kind == 0 ? bq   : kind == 1 ? bk   : bv;

    const int lr  = tid >> 2;
    const int lch = (tid & 3) * 8;
    const __half* Ag = g_x + (size_t)(bm + lr) * K + lch;
    const __half* Wg = Wbase + (size_t)(bn + lr) * K + lch;
    const int so = lr*GH + lch;

    const uint32_t asmb = (uint32_t)__cvta_generic_to_shared(&As[0][0]);
    const uint32_t bsmb = (uint32_t)__cvta_generic_to_shared(&Bs[0][0]);
    const int qq = lane >> 3, rr = lane & 7;
    const int aoff = ((wm*32 + (qq & 1)*8 + rr)*GH + (qq >> 1)*8) * 2;
    const int boff = ((wn*64 + (qq >> 1)*8 + rr)*GH + (qq & 1)*8) * 2;

    float acc[2][8][4];
    #pragma unroll
    for (int m = 0; m < 2; m++)
        #pragma unroll
        for (int nb = 0; nb < 8; nb++)
            #pragma unroll
            for (int r = 0; r < 4; r++) acc[m][nb][r] = 0.f;

    const int nk = K / 32;
    {
        cp16h(&As[0][so],          Ag);
        cp16h(&As[0][so + 64*GH],  Ag + (size_t)64*K);
        cp16h(&Bs[0][so],          Wg);
        cp16h(&Bs[0][so + 64*GH],  Wg + (size_t)64*K);
        asm volatile("cp.async.commit_group;\n");
    }

    for (int i = 0; i < nk; i++) {
        const int buf = i & 1;
        if (i + 1 < nk) {
            int ko = (i + 1) * 32;
            cp16h(&As[buf^1][so],         Ag + ko);
            cp16h(&As[buf^1][so + 64*GH], Ag + (size_t)64*K + ko);
            cp16h(&Bs[buf^1][so],         Wg + ko);
            cp16h(&Bs[buf^1][so + 64*GH], Wg + (size_t)64*K + ko);
            asm volatile("cp.async.commit_group;\n");
            asm volatile("cp.async.wait_group 1;\n");
        } else {
            asm volatile("cp.async.wait_group 0;\n");
        }
        __syncthreads();

        const uint32_t Abase = asmb + buf*(128*GH*2) + aoff;
        const uint32_t Bbase = bsmb + buf*(128*GH*2) + boff;
        #pragma unroll
        for (int kc = 0; kc < 2; kc++) {
            uint32_t a[2][4];
            ldsm_x4(a[0][0], a[0][1], a[0][2], a[0][3], Abase + kc*32);
            ldsm_x4(a[1][0], a[1][1], a[1][2], a[1][3],
                    Abase + 16*GH*2 + kc*32);
            #pragma unroll
            for (int nbp = 0; nbp < 4; nbp++) {
                uint32_t b0, b1, c0, c1;
                ldsm_x4(b0, b1, c0, c1, Bbase + nbp*(16*GH*2) + kc*32);
                mma_f16(acc[0][2*nbp][0], acc[0][2*nbp][1],
                        acc[0][2*nbp][2], acc[0][2*nbp][3],
                        a[0][0], a[0][1], a[0][2], a[0][3], b0, b1);
                mma_f16(acc[1][2*nbp][0], acc[1][2*nbp][1],
                        acc[1][2*nbp][2], acc[1][2*nbp][3],
                        a[1][0], a[1][1], a[1][2], a[1][3], b0, b1);
                mma_f16(acc[0][2*nbp+1][0], acc[0][2*nbp+1][1],
                        acc[0][2*nbp+1][2], acc[0][2*nbp+1][3],
                        a[0][0], a[0][1], a[0][2], a[0][3], c0, c1);
                mma_f16(acc[1][2*nbp+1][0], acc[1][2*nbp+1][1],
                        acc[1][2*nbp+1][2], acc[1][2*nbp+1][3],
                        a[1][0], a[1][1], a[1][2], a[1][3], c0, c1);
            }
        }
        __syncthreads();
    }

    const int head  = (bn + wn*64) >> 6;
    const int bcol  = bn + wn*64;
    const float qsc = (kind == 0) ? 0.125f * 1.4426950408889634f : 1.f;

    #pragma unroll
    for (int m = 0; m < 2; m++) {
        #pragma unroll
        for (int hh = 0; hh < 2; hh++) {
            int row = bm + wm*32 + m*16 + g + hh*8;
            int bb  = row >> 12;
            int ss  = row & (S_ - 1);
            #pragma unroll
            for (int nbl = 0; nbl < 4; nbl++) {
                int c = nbl*8 + 2*t;
                float lo0 = acc[m][nbl  ][hh*2+0] + bias[bcol + c];
                float lo1 = acc[m][nbl  ][hh*2+1] + bias[bcol + c + 1];
                float hi0 = acc[m][nbl+4][hh*2+0] + bias[bcol + c + 32];
                float hi1 = acc[m][nbl+4][hh*2+1] + bias[bcol + c + 33];
                if (kind == 2) {
                    __half* dv = g_vT + ((size_t)(bb*H_ + head)*D_)*S_ + ss;
                    dv[(size_t)(c     )*S_] = __float2half_rn(lo0);
                    dv[(size_t)(c +  1)*S_] = __float2half_rn(lo1);
                    dv[(size_t)(c + 32)*S_] = __float2half_rn(hi0);
                    dv[(size_t)(c + 33)*S_] = __float2half_rn(hi1);
                } else {
                    float2 cs0 = g_cs[ss*32 + c];
                    float2 cs1 = g_cs[ss*32 + c + 1];
                    float o_lo0 = (lo0*cs0.x - hi0*cs0.y) * qsc;
                    float o_hi0 = (hi0*cs0.x + lo0*cs0.y) * qsc;
                    float o_lo1 = (lo1*cs1.x - hi1*cs1.y) * qsc;
                    float o_hi1 = (hi1*cs1.x + lo1*cs1.y) * qsc;
                    __half* dst = (kind == 0 ? g_q : g_k)
                                + ((size_t)(bb*H_ + head)*S_ + ss)*D_;
                    *(__half2*)&dst[c]      = __floats2half2_rn(o_lo0, o_lo1);
                    *(__half2*)&dst[c + 32] = __floats2half2_rn(o_hi0, o_hi1);
                }
            }
        }
    }
}

// ============================================================================
// fp16 GEMM (out-projection), ldmatrix fragments.  (unchanged)
// ============================================================================
__global__ __launch_bounds__(256, 2) void gemm_f16_kernel(
    const __half* __restrict__ A, const __half* __restrict__ W,
    const float* __restrict__ bias, float* __restrict__ C,
    int M, int N, int K)
{
    __shared__ __align__(16) __half As[2][128*GH];
    __shared__ __align__(16) __half Bs[2][128*GH];

    const int tid  = threadIdx.x;
    const int w    = tid >> 5;
    const int lane = tid & 31;
    const int g    = lane >> 2;
    const int t    = lane & 3;
    const int wm   = w >> 1;
    const int wn   = w & 1;
    const int bm   = blockIdx.y * 128;
    const int bn   = blockIdx.x * 128;

    const int lr  = tid >> 2;
    const int lch = (tid & 3) * 8;
    const __half* Ag = A + (size_t)(bm + lr) * K + lch;
    const __half* Wg = W + (size_t)(bn + lr) * K + lch;
    const int so = lr*GH + lch;

    const uint32_t asmb = (uint32_t)__cvta_generic_to_shared(&As[0][0]);
    const uint32_t bsmb = (uint32_t)__cvta_generic_to_shared(&Bs[0][0]);
    const int qq = lane >> 3, rr = lane & 7;
    const int aoff = ((wm*32 + (qq & 1)*8 + rr)*GH + (qq >> 1)*8) * 2;
    const int boff = ((wn*64 + (qq >> 1)*8 + rr)*GH + (qq & 1)*8) * 2;

    float acc[2][8][4];
    #pragma unroll
    for (int m = 0; m < 2; m++)
        #pragma unroll
        for (int nb = 0; nb < 8; nb++)
            #pragma unroll
            for (int r = 0; r < 4; r++) acc[m][nb][r] = 0.f;

    const int nk = K / 32;
    {
        cp16h(&As[0][so],         Ag);
        cp16h(&As[0][so + 64*GH], Ag + (size_t)64*K);
        cp16h(&Bs[0][so],         Wg);
        cp16h(&Bs[0][so + 64*GH], Wg + (size_t)64*K);
        asm volatile("cp.async.commit_group;\n");
    }

    for (int i = 0; i < nk; i++) {
        const int buf = i & 1;
        if (i + 1 < nk) {
            int ko = (i + 1) * 32;
            cp16h(&As[buf^1][so],         Ag + ko);
            cp16h(&As[buf^1][so + 64*GH], Ag + (size_t)64*K + ko);
            cp16h(&Bs[buf^1][so],         Wg + ko);
            cp16h(&Bs[buf^1][so + 64*GH], Wg + (size_t)64*K + ko);
            asm volatile("cp.async.commit_group;\n");
            asm volatile("cp.async.wait_group 1;\n");
        } else {
            asm volatile("cp.async.wait_group 0;\n");
        }
        __syncthreads();

        const uint32_t Abase = asmb + buf*(128*GH*2) + aoff;
        const uint32_t Bbase = bsmb + buf*(128*GH*2) + boff;
        #pragma unroll
        for (int kc = 0; kc < 2; kc++) {
            uint32_t a[2][4];
            ldsm_x4(a[0][0], a[0][1], a[0][2], a[0][3], Abase + kc*32);
            ldsm_x4(a[1][0], a[1][1], a[1][2], a[1][3],
                    Abase + 16*GH*2 + kc*32);
            #pragma unroll
            for (int nbp = 0; nbp < 4; nbp++) {
                uint32_t b0, b1, c0, c1;
                ldsm_x4(b0, b1, c0, c1, Bbase + nbp*(16*GH*2) + kc*32);
                mma_f16(acc[0][2*nbp][0], acc[0][2*nbp][1],
                        acc[0][2*nbp][2], acc[0][2*nbp][3],
                        a[0][0], a[0][1], a[0][2], a[0][3], b0, b1);
                mma_f16(acc[1][2*nbp][0], acc[1][2*nbp][1],
                        acc[1][2*nbp][2], acc[1][2*nbp][3],
                        a[1][0], a[1][1], a[1][2], a[1][3], b0, b1);
                mma_f16(acc[0][2*nbp+1][0], acc[0][2*nbp+1][1],
                        acc[0][2*nbp+1][2], acc[0][2*nbp+1][3],
                        a[0][0], a[0][1], a[0][2], a[0][3], c0, c1);
                mma_f16(acc[1][2*nbp+1][0], acc[1][2*nbp+1][1],
                        acc[1][2*nbp+1][2], acc[1][2*nbp+1][3],
                        a[1][0], a[1][1], a[1][2], a[1][3], c0, c1);
            }
        }
        __syncthreads();
    }

    #pragma unroll
    for (int m = 0; m < 2; m++) {
        int row = bm + wm*32 + m*16 + g;
        #pragma unroll
        for (int nb = 0; nb < 8; nb++) {
            int n = bn + wn*64 + nb*8 + 2*t;
            float2 bb = *(const float2*)&bias[n];
            *(float2*)&C[(size_t)row*N + n] =
                make_float2(acc[m][nb][0] + bb.x, acc[m][nb][1] + bb.y);
            *(float2*)&C[(size_t)(row+8)*N + n] =
                make_float2(acc[m][nb][2] + bb.x, acc[m][nb][3] + bb.y);
        }
    }
}

// ============================================================================
// Causal flash attention, fp16 mma + ldmatrix/stmatrix + f16x2 softmax.
// Row sums computed by an extra ones-column MMA (V rows 64-79: row64=1, rest
// 0), accumulating l in fp32 across all iterations — no shuffle reductions.
// Grid (32, 16), largest Q tile first.
// ============================================================================
#define STH 72    // halves; rows 144B apart -> LDSM conflict-free
#define VROWS 80  // 64 d rows + 16 extra (row 64 = ones)
#define SMEM_ATT ((128*STH + 2*64*STH + 2*VROWS*STH) * (int)sizeof(__half))

__global__ __launch_bounds__(256, 2) void attn_mma_kernel()
{
    extern __shared__ __half smh[];
    __half* Ps  = smh;                   // 128 x STH (Q staging in prologue)
    __half* Ks0 = Ps + 128*STH;          // 2 x 64 x STH
    __half* Vs0 = Ks0 + 2*64*STH;        // 2 x VROWS x STH  ([d][j])

    const int tid  = threadIdx.x;
    const int w    = tid >> 5;
    const int lane = tid & 31;
    const int g    = lane >> 2;
    const int t    = lane & 3;
    const int bh   = blockIdx.y;
    const int it   = (int)gridDim.x - 1 - (int)blockIdx.x;

    const __half* qb = g_q  + (size_t)bh*S_*D_ + (size_t)it*128*D_;
    const __half* kb = g_k  + (size_t)bh*S_*D_;
    const __half* vb = g_vT + (size_t)bh*D_*S_;

    const uint32_t psm = (uint32_t)__cvta_generic_to_shared(Ps);
    const uint32_t ksm = (uint32_t)__cvta_generic_to_shared(Ks0);
    const uint32_t vsm = (uint32_t)__cvta_generic_to_shared(Vs0);

    const int qq = lane >> 3;
    const int rr = lane & 7;
    const int b_off = (((qq >> 1)*8 + rr)*STH + (qq & 1)*8) * 2;
    const int a_off = ((w*16 + (qq & 1)*8 + rr)*STH + (qq >> 1)*8) * 2;

    const int klr = tid >> 2;
    const int klc = (tid & 3) * 16;

    // prefetch KV tile 0
    {
        const __half* kr = kb + (size_t)klr*D_ + klc;
        const __half* vr = vb + (size_t)klr*S_ + klc;
        cp16h(&Ks0[klr*STH + klc],     kr);
        cp16h(&Ks0[klr*STH + klc + 8], kr + 8);
        cp16h(&Vs0[klr*STH + klc],     vr);
        cp16h(&Vs0[klr*STH + klc + 8], vr + 8);
        asm volatile("cp.async.commit_group;\n");
    }

    // fill V extra rows (both buffers): row 64 = 1.0, rows 65-79 = 0
    for (int i = tid; i < 2*16*STH; i += 256) {
        int b = i / (16*STH);
        int r = (i % (16*STH)) / STH;
        int c = i % STH;
        Vs0[b*VROWS*STH + (64 + r)*STH + c] =
            __float2half(r == 0 ? 1.f : 0.f);
    }

    // stage Q, lift fragments
    {
        int lr = tid >> 1, lc = (tid & 1)*32;
        #pragma unroll
        for (int i = 0; i < 4; i++)
            *(float4*)&Ps[lr*STH + lc + i*8] = *(const float4*)&qb[lr*D_ + lc + i*8];
    }
    __syncthreads();

    const int row_a = w*16 + g;
    const int row_b = row_a + 8;
    const int gi_a  = it*128 + row_a;
    const int gi_b  = it*128 + row_b;

    uint32_t qf[4][4];
    #pragma unroll
    for (int kc = 0; kc < 4; kc++)
        ldsm_x4(qf[kc][0], qf[kc][1], qf[kc][2], qf[kc][3],
                psm + kc*32 + a_off);
    __syncthreads();   // Ps free for P

    float oc[8][4];
    #pragma unroll
    for (int nb = 0; nb < 8; nb++)
        #pragma unroll
        for (int r = 0; r < 4; r++) oc[nb][r] = 0.f;
    float lacc[4] = {0.f, 0.f, 0.f, 0.f};   // ones-column accumulator

    const int njt = 2*it + 2;

    for (int jt = 0; jt < njt; jt++) {
        const int buf = jt & 1;
        asm volatile("cp.async.wait_group 0;\n");
        __syncthreads();

        if (jt + 1 < njt) {
            const __half* kr = kb + (size_t)((jt+1)*64 + klr)*D_ + klc;
            const __half* vr = vb + (size_t)klr*S_ + (jt+1)*64 + klc;
            __half* Kd = Ks0 + (buf^1)*64*STH;
            __half* Vd = Vs0 + (buf^1)*VROWS*STH;
            cp16h(&Kd[klr*STH + klc],     kr);
            cp16h(&Kd[klr*STH + klc + 8], kr + 8);
            cp16h(&Vd[klr*STH + klc],     vr);
            cp16h(&Vd[klr*STH + klc + 8], vr + 8);
            asm volatile("cp.async.commit_group;\n");
        }

        const uint32_t kbase = ksm + buf*(64*STH*2)    + b_off;
        const uint32_t vbase = vsm + buf*(VROWS*STH*2) + b_off;

        // ---- S = Q K^T ----
        float sc[8][4];
        #pragma unroll
        for (int nb = 0; nb < 8; nb++)
            #pragma unroll
            for (int r = 0; r < 4; r++) sc[nb][r] = 0.f;

        #pragma unroll
        for (int kc = 0; kc < 4; kc++) {
            #pragma unroll
            for (int nbp = 0; nbp < 4; nbp++) {
                uint32_t b0, b1, c0, c1;
                ldsm_x4(b0, b1, c0, c1, kbase + nbp*(16*STH*2) + kc*32);
                mma_f16(sc[2*nbp][0], sc[2*nbp][1], sc[2*nbp][2], sc[2*nbp][3],
                        qf[kc][0], qf[kc][1], qf[kc][2], qf[kc][3], b0, b1);
                mma_f16(sc[2*nbp+1][0], sc[2*nbp+1][1], sc[2*nbp+1][2], sc[2*nbp+1][3],
                        qf[kc][0], qf[kc][1], qf[kc][2], qf[kc][3], c0, c1);
            }
        }

        // ---- causal mask (-30: 2^-30 underflows half -> exactly 0) ----
        if (jt >= 2*it) {
            int jbase = jt*64;
            #pragma unroll
            for (int nb = 0; nb < 8; nb++) {
                int j0 = jbase + nb*8 + 2*t;
                if (j0     > gi_a) sc[nb][0] = -30.f;
                if (j0 + 1 > gi_a) sc[nb][1] = -30.f;
                if (j0     > gi_b) sc[nb][2] = -30.f;
                if (j0 + 1 > gi_b) sc[nb][3] = -30.f;
            }
        }

        // ---- softmax numerator: pack to half2, ex2.approx.f16x2 ----
        uint32_t ph0[8], ph1[8];
        #pragma unroll
        for (int nb = 0; nb < 8; nb++) {
            ph0[nb] = h2ex2(pack2(sc[nb][0], sc[nb][1]));
            ph1[nb] = h2ex2(pack2(sc[nb][2], sc[nb][3]));
        }
        #pragma unroll
        for (int j = 0; j < 4; j++)
            stsm_x4(psm + j*32 + a_off,
                    ph0[2*j], ph1[2*j], ph0[2*j+1], ph1[2*j+1]);
        __syncwarp();   // P rows warp-private

        // ---- O += P V  (+ ones-column mma accumulates row sums) ----
        #pragma unroll
        for (int kc = 0; kc < 4; kc++) {
            uint32_t a0, a1, a2, a3;
            ldsm_x4(a0, a1, a2, a3, psm + kc*32 + a_off);
            #pragma unroll
            for (int nbp = 0; nbp < 4; nbp++) {
                uint32_t b0, b1, c0, c1;
                ldsm_x4(b0, b1, c0, c1, vbase + nbp*(16*STH*2) + kc*32);
                mma_f16(oc[2*nbp][0], oc[2*nbp][1], oc[2*nbp][2], oc[2*nbp][3],
                        a0, a1, a2, a3, b0, b1);
                mma_f16(oc[2*nbp+1][0], oc[2*nbp+1][1], oc[2*nbp+1][2], oc[2*nbp+1][3],
                        a0, a1, a2, a3, c0, c1);
            }
            {   // ones rows 64-71 (72-79 are zeros; second mma skipped)
                uint32_t e0, e1, e2, e3;
                ldsm_x4(e0, e1, e2, e3, vbase + 4*(16*STH*2) + kc*32);
                mma_f16(lacc[0], lacc[1], lacc[2], lacc[3],
                        a0, a1, a2, a3, e0, e1);
            }
        }
        __syncwarp();
    }

    // ---- epilogue: l lives in t=0 lanes (column n=64); broadcast ----
    {
        int src = lane & ~3;   // lane of t=0 in this quad
        float l_a = __shfl_sync(0xffffffffu, lacc[0], src);
        float l_b = __shfl_sync(0xffffffffu, lacc[2], src);
        float inva = 1.f / l_a, invb = 1.f / l_b;
        int b = bh >> 3, h = bh & 7;
        __half* da = g_att + (size_t)(b*S_ + gi_a)*DM_ + h*D_;
        __half* db = g_att + (size_t)(b*S_ + gi_b)*DM_ + h*D_;
        #pragma unroll
        for (int nb = 0; nb < 8; nb++) {
            *(__half2*)&da[nb*8 + 2*t] =
                __floats2half2_rn(oc[nb][0]*inva, oc[nb][1]*inva);
            *(__half2*)&db[nb*8 + 2*t] =
                __floats2half2_rn(oc[nb][2]*invb, oc[nb][3]*invb);
        }
    }
}

// ============================================================================
extern "C" void kernel_launch(void* const* d_in, const int* in_sizes, int n_in,
                              void* d_out, int out_size)
{
    const float* x  = (const float*)d_in[0];
    const float* Wq = (const float*)d_in[2];
    const float* bq = (const float*)d_in[3];
    const float* Wk = (const float*)d_in[4];
    const float* bk = (const float*)d_in[5];
    const float* Wv = (const float*)d_in[6];
    const float* bv = (const float*)d_in[7];
    const float* Wo = (const float*)d_in[8];
    const float* bo = (const float*)d_in[9];
    float* out = (float*)d_out;

    __half *wo, *att;
    cudaGetSymbolAddress((void**)&wo,  g_wo);
    cudaGetSymbolAddress((void**)&att, g_att);

    prep_kernel<<<5632, 256>>>(x, Wq, Wk, Wv, Wo);

    qkv_rope_kernel<<<dim3(12, ROWS_/128), 256>>>(bq, bk, bv);

    cudaFuncSetAttribute(attn_mma_kernel,
                         cudaFuncAttributeMaxDynamicSharedMemorySize, SMEM_ATT);
    attn_mma_kernel<<<dim3(S_/128, B_*H_), 256, SMEM_ATT>>>();

    gemm_f16_kernel<<<dim3(DM_/128, ROWS_/128), 256>>>(att, wo, bo, out,
                                                       ROWS_, DM_, DM_);
}

// round 12
// speedup vs baseline: 1.0758x; 1.0758x over previous
#include <cuda_runtime.h>
#include <cuda_fp16.h>
#include <math.h>
#include <stdint.h>

#define B_    2
#define H_    8
#define S_    4096
#define D_    64
#define DM_   512
#define ROWS_ (B_*S_)   // 8192

// ---- scratch (static __device__ arrays; no allocation allowed) ----
__device__ __half g_x [ROWS_*DM_];
__device__ __half g_wq[DM_*DM_];
__device__ __half g_wk[DM_*DM_];
__device__ __half g_wv[DM_*DM_];
__device__ __half g_wo[DM_*DM_];
__device__ __half g_q [B_*H_*S_*D_];   // [B,H,S,D] (Q pre-scaled 1/8*log2e)
__device__ __half g_k [B_*H_*S_*D_];   // [B,H,S,D]
__device__ __half g_vT[B_*H_*D_*S_];   // [B,H,D,S] (transposed)
__device__ __half g_att[ROWS_*DM_];    // attention out, [B,S,H*D]
__device__ float2 g_cs[S_*32];         // (cos, sin) per (s, d2)

__device__ __forceinline__ void cp16h(__half* s, const __half* g) {
    uint32_t sa = (uint32_t)__cvta_generic_to_shared(s);
    asm volatile("cp.async.cg.shared.global [%0], [%1], 16;\n" :: "r"(sa), "l"(g));
}

__device__ __forceinline__ void mma_f16(
    float& c0, float& c1, float& c2, float& c3,
    uint32_t a0, uint32_t a1, uint32_t a2, uint32_t a3,
    uint32_t b0, uint32_t b1)
{
    asm volatile(
        "mma.sync.aligned.m16n8k16.row.col.f32.f16.f16.f32 "
        "{%0,%1,%2,%3}, {%4,%5,%6,%7}, {%8,%9}, {%0,%1,%2,%3};"
        : "+f"(c0), "+f"(c1), "+f"(c2), "+f"(c3)
        : "r"(a0), "r"(a1), "r"(a2), "r"(a3), "r"(b0), "r"(b1));
}

__device__ __forceinline__ void ldsm_x4(
    uint32_t& r0, uint32_t& r1, uint32_t& r2, uint32_t& r3, uint32_t addr)
{
    asm volatile(
        "ldmatrix.sync.aligned.m8n8.x4.shared.b16 {%0,%1,%2,%3}, [%4];"
        : "=r"(r0), "=r"(r1), "=r"(r2), "=r"(r3) : "r"(addr));
}

__device__ __forceinline__ uint32_t pack2(float a, float b) {
    __half2 h = __floats2half2_rn(a, b);
    return *reinterpret_cast<uint32_t*>(&h);
}

__device__ __forceinline__ uint32_t h2ex2(uint32_t x) {
    uint32_t y;
    asm("ex2.approx.f16x2 %0, %1;" : "=r"(y) : "r"(x));
    return y;
}

__device__ __forceinline__ __half2 u2h(uint32_t x) {
    return *reinterpret_cast<__half2*>(&x);
}

// ============================================================================
// One fused prep kernel: fp16-round x & weights + cos/sin table.
// ============================================================================
#define NW4 (DM_*DM_/4)
__global__ __launch_bounds__(256) void prep_kernel(
    const float* __restrict__ x,
    const float* __restrict__ wq, const float* __restrict__ wk,
    const float* __restrict__ wv, const float* __restrict__ wo)
{
    int bx = blockIdx.x;
    if (bx < 4096) {
        int i = bx*256 + threadIdx.x;
        float4 v = ((const float4*)x)[i];
        ((__half2*)g_x)[i*2]   = __floats2half2_rn(v.x, v.y);
        ((__half2*)g_x)[i*2+1] = __floats2half2_rn(v.z, v.w);
    } else if (bx < 5120) {
        int idx = (bx - 4096)*256 + threadIdx.x;
        int seg = idx >> 16;
        int i   = idx & (NW4 - 1);
        const float* src = seg == 0 ? wq : seg == 1 ? wk : seg == 2 ? wv : wo;
        __half* dst      = seg == 0 ? g_wq : seg == 1 ? g_wk : seg == 2 ? g_wv : g_wo;
        float4 v = ((const float4*)src)[i];
        ((__half2*)dst)[i*2]   = __floats2half2_rn(v.x, v.y);
        ((__half2*)dst)[i*2+1] = __floats2half2_rn(v.z, v.w);
    } else {
        int id = (bx - 5120)*256 + threadIdx.x;
        int d2 = id & 31, s = id >> 5;
        double invf = exp2(-(double)d2 * (13.287712379549449 / 32.0));
        double ph   = (double)s * invf;
        double n    = rint(ph * 0.15915494309189535);
        float  r    = (float)(ph - 6.283185307179586 * n);
        float sn, cs;
        sincosf(r, &sn, &cs);
        g_cs[id] = make_float2(cs, sn);
    }
}

// ============================================================================
// Fused QKV GEMM + bias + RoPE + transpose; fp16 in/out; ldmatrix fragments.
// Q scaled by (1/8)*log2(e) so attention softmax can use ex2 directly.
// ============================================================================
#define GH 40   // halves; rows 80B -> LDSM phases all distinct mod 128

__global__ __launch_bounds__(256, 2) void qkv_rope_kernel(
    const float* __restrict__ bq, const float* __restrict__ bk,
    const float* __restrict__ bv)
{
    __shared__ __align__(16) __half As[2][128*GH];
    __shared__ __align__(16) __half Bs[2][128*GH];

    const int tid  = threadIdx.x;
    const int w    = tid >> 5;
    const int lane = tid & 31;
    const int g    = lane >> 2;
    const int t    = lane & 3;
    const int wm   = w >> 1;
    const int wn   = w & 1;
    const int bm   = blockIdx.y * 128;
    const int kind = blockIdx.x >> 2;
    const int bn   = (blockIdx.x & 3) * 128;
    const int K    = DM_;

    const __half* Wbase = kind == 0 ? g_wq : kind == 1 ? g_wk : g_wv;
    const float*  bias  = kind == 0 ? bq   : kind == 1 ? bk   : bv;

    const int lr  = tid >> 2;
    const int lch = (tid & 3) * 8;
    const __half* Ag = g_x + (size_t)(bm + lr) * K + lch;
    const __half* Wg = Wbase + (size_t)(bn + lr) * K + lch;
    const int so = lr*GH + lch;

    const uint32_t asmb = (uint32_t)__cvta_generic_to_shared(&As[0][0]);
    const uint32_t bsmb = (uint32_t)__cvta_generic_to_shared(&Bs[0][0]);
    const int qq = lane >> 3, rr = lane & 7;
    const int aoff = ((wm*32 + (qq & 1)*8 + rr)*GH + (qq >> 1)*8) * 2;
    const int boff = ((wn*64 + (qq >> 1)*8 + rr)*GH + (qq & 1)*8) * 2;

    float acc[2][8][4];
    #pragma unroll
    for (int m = 0; m < 2; m++)
        #pragma unroll
        for (int nb = 0; nb < 8; nb++)
            #pragma unroll
            for (int r = 0; r < 4; r++) acc[m][nb][r] = 0.f;

    const int nk = K / 32;
    {
        cp16h(&As[0][so],          Ag);
        cp16h(&As[0][so + 64*GH],  Ag + (size_t)64*K);
        cp16h(&Bs[0][so],          Wg);
        cp16h(&Bs[0][so + 64*GH],  Wg + (size_t)64*K);
        asm volatile("cp.async.commit_group;\n");
    }

    for (int i = 0; i < nk; i++) {
        const int buf = i & 1;
        if (i + 1 < nk) {
            int ko = (i + 1) * 32;
            cp16h(&As[buf^1][so],         Ag + ko);
            cp16h(&As[buf^1][so + 64*GH], Ag + (size_t)64*K + ko);
            cp16h(&Bs[buf^1][so],         Wg + ko);
            cp16h(&Bs[buf^1][so + 64*GH], Wg + (size_t)64*K + ko);
            asm volatile("cp.async.commit_group;\n");
            asm volatile("cp.async.wait_group 1;\n");
        } else {
            asm volatile("cp.async.wait_group 0;\n");
        }
        __syncthreads();

        const uint32_t Abase = asmb + buf*(128*GH*2) + aoff;
        const uint32_t Bbase = bsmb + buf*(128*GH*2) + boff;
        #pragma unroll
        for (int kc = 0; kc < 2; kc++) {
            uint32_t a[2][4];
            ldsm_x4(a[0][0], a[0][1], a[0][2], a[0][3], Abase + kc*32);
            ldsm_x4(a[1][0], a[1][1], a[1][2], a[1][3],
                    Abase + 16*GH*2 + kc*32);
            #pragma unroll
            for (int nbp = 0; nbp < 4; nbp++) {
                uint32_t b0, b1, c0, c1;
                ldsm_x4(b0, b1, c0, c1, Bbase + nbp*(16*GH*2) + kc*32);
                mma_f16(acc[0][2*nbp][0], acc[0][2*nbp][1],
                        acc[0][2*nbp][2], acc[0][2*nbp][3],
                        a[0][0], a[0][1], a[0][2], a[0][3], b0, b1);
                mma_f16(acc[1][2*nbp][0], acc[1][2*nbp][1],
                        acc[1][2*nbp][2], acc[1][2*nbp][3],
                        a[1][0], a[1][1], a[1][2], a[1][3], b0, b1);
                mma_f16(acc[0][2*nbp+1][0], acc[0][2*nbp+1][1],
                        acc[0][2*nbp+1][2], acc[0][2*nbp+1][3],
                        a[0][0], a[0][1], a[0][2], a[0][3], c0, c1);
                mma_f16(acc[1][2*nbp+1][0], acc[1][2*nbp+1][1],
                        acc[1][2*nbp+1][2], acc[1][2*nbp+1][3],
                        a[1][0], a[1][1], a[1][2], a[1][3], c0, c1);
            }
        }
        __syncthreads();
    }

    const int head  = (bn + wn*64) >> 6;
    const int bcol  = bn + wn*64;
    const float qsc = (kind == 0) ? 0.125f * 1.4426950408889634f : 1.f;

    #pragma unroll
    for (int m = 0; m < 2; m++) {
        #pragma unroll
        for (int hh = 0; hh < 2; hh++) {
            int row = bm + wm*32 + m*16 + g + hh*8;
            int bb  = row >> 12;
            int ss  = row & (S_ - 1);
            #pragma unroll
            for (int nbl = 0; nbl < 4; nbl++) {
                int c = nbl*8 + 2*t;
                float lo0 = acc[m][nbl  ][hh*2+0] + bias[bcol + c];
                float lo1 = acc[m][nbl  ][hh*2+1] + bias[bcol + c + 1];
                float hi0 = acc[m][nbl+4][hh*2+0] + bias[bcol + c + 32];
                float hi1 = acc[m][nbl+4][hh*2+1] + bias[bcol + c + 33];
                if (kind == 2) {
                    __half* dv = g_vT + ((size_t)(bb*H_ + head)*D_)*S_ + ss;
                    dv[(size_t)(c     )*S_] = __float2half_rn(lo0);
                    dv[(size_t)(c +  1)*S_] = __float2half_rn(lo1);
                    dv[(size_t)(c + 32)*S_] = __float2half_rn(hi0);
                    dv[(size_t)(c + 33)*S_] = __float2half_rn(hi1);
                } else {
                    float2 cs0 = g_cs[ss*32 + c];
                    float2 cs1 = g_cs[ss*32 + c + 1];
                    float o_lo0 = (lo0*cs0.x - hi0*cs0.y) * qsc;
                    float o_hi0 = (hi0*cs0.x + lo0*cs0.y) * qsc;
                    float o_lo1 = (lo1*cs1.x - hi1*cs1.y) * qsc;
                    float o_hi1 = (hi1*cs1.x + lo1*cs1.y) * qsc;
                    __half* dst = (kind == 0 ? g_q : g_k)
                                + ((size_t)(bb*H_ + head)*S_ + ss)*D_;
                    *(__half2*)&dst[c]      = __floats2half2_rn(o_lo0, o_lo1);
                    *(__half2*)&dst[c + 32] = __floats2half2_rn(o_hi0, o_hi1);
                }
            }
        }
    }
}

// ============================================================================
// fp16 GEMM (out-projection), ldmatrix fragments.  (unchanged)
// ============================================================================
__global__ __launch_bounds__(256, 2) void gemm_f16_kernel(
    const __half* __restrict__ A, const __half* __restrict__ W,
    const float* __restrict__ bias, float* __restrict__ C,
    int M, int N, int K)
{
    __shared__ __align__(16) __half As[2][128*GH];
    __shared__ __align__(16) __half Bs[2][128*GH];

    const int tid  = threadIdx.x;
    const int w    = tid >> 5;
    const int lane = tid & 31;
    const int g    = lane >> 2;
    const int t    = lane & 3;
    const int wm   = w >> 1;
    const int wn   = w & 1;
    const int bm   = blockIdx.y * 128;
    const int bn   = blockIdx.x * 128;

    const int lr  = tid >> 2;
    const int lch = (tid & 3) * 8;
    const __half* Ag = A + (size_t)(bm + lr) * K + lch;
    const __half* Wg = W + (size_t)(bn + lr) * K + lch;
    const int so = lr*GH + lch;

    const uint32_t asmb = (uint32_t)__cvta_generic_to_shared(&As[0][0]);
    const uint32_t bsmb = (uint32_t)__cvta_generic_to_shared(&Bs[0][0]);
    const int qq = lane >> 3, rr = lane & 7;
    const int aoff = ((wm*32 + (qq & 1)*8 + rr)*GH + (qq >> 1)*8) * 2;
    const int boff = ((wn*64 + (qq >> 1)*8 + rr)*GH + (qq & 1)*8) * 2;

    float acc[2][8][4];
    #pragma unroll
    for (int m = 0; m < 2; m++)
        #pragma unroll
        for (int nb = 0; nb < 8; nb++)
            #pragma unroll
            for (int r = 0; r < 4; r++) acc[m][nb][r] = 0.f;

    const int nk = K / 32;
    {
        cp16h(&As[0][so],         Ag);
        cp16h(&As[0][so + 64*GH], Ag + (size_t)64*K);
        cp16h(&Bs[0][so],         Wg);
        cp16h(&Bs[0][so + 64*GH], Wg + (size_t)64*K);
        asm volatile("cp.async.commit_group;\n");
    }

    for (int i = 0; i < nk; i++) {
        const int buf = i & 1;
        if (i + 1 < nk) {
            int ko = (i + 1) * 32;
            cp16h(&As[buf^1][so],         Ag + ko);
            cp16h(&As[buf^1][so + 64*GH], Ag + (size_t)64*K + ko);
            cp16h(&Bs[buf^1][so],         Wg + ko);
            cp16h(&Bs[buf^1][so + 64*GH], Wg + (size_t)64*K + ko);
            asm volatile("cp.async.commit_group;\n");
            asm volatile("cp.async.wait_group 1;\n");
        } else {
            asm volatile("cp.async.wait_group 0;\n");
        }
        __syncthreads();

        const uint32_t Abase = asmb + buf*(128*GH*2) + aoff;
        const uint32_t Bbase = bsmb + buf*(128*GH*2) + boff;
        #pragma unroll
        for (int kc = 0; kc < 2; kc++) {
            uint32_t a[2][4];
            ldsm_x4(a[0][0], a[0][1], a[0][2], a[0][3], Abase + kc*32);
            ldsm_x4(a[1][0], a[1][1], a[1][2], a[1][3],
                    Abase + 16*GH*2 + kc*32);
            #pragma unroll
            for (int nbp = 0; nbp < 4; nbp++) {
                uint32_t b0, b1, c0, c1;
                ldsm_x4(b0, b1, c0, c1, Bbase + nbp*(16*GH*2) + kc*32);
                mma_f16(acc[0][2*nbp][0], acc[0][2*nbp][1],
                        acc[0][2*nbp][2], acc[0][2*nbp][3],
                        a[0][0], a[0][1], a[0][2], a[0][3], b0, b1);
                mma_f16(acc[1][2*nbp][0], acc[1][2*nbp][1],
                        acc[1][2*nbp][2], acc[1][2*nbp][3],
                        a[1][0], a[1][1], a[1][2], a[1][3], b0, b1);
                mma_f16(acc[0][2*nbp+1][0], acc[0][2*nbp+1][1],
                        acc[0][2*nbp+1][2], acc[0][2*nbp+1][3],
                        a[0][0], a[0][1], a[0][2], a[0][3], c0, c1);
                mma_f16(acc[1][2*nbp+1][0], acc[1][2*nbp+1][1],
                        acc[1][2*nbp+1][2], acc[1][2*nbp+1][3],
                        a[1][0], a[1][1], a[1][2], a[1][3], c0, c1);
            }
        }
        __syncthreads();
    }

    #pragma unroll
    for (int m = 0; m < 2; m++) {
        int row = bm + wm*32 + m*16 + g;
        #pragma unroll
        for (int nb = 0; nb < 8; nb++) {
            int n = bn + wn*64 + nb*8 + 2*t;
            float2 bb = *(const float2*)&bias[n];
            *(float2*)&C[(size_t)row*N + n] =
                make_float2(acc[m][nb][0] + bb.x, acc[m][nb][1] + bb.y);
            *(float2*)&C[(size_t)(row+8)*N + n] =
                make_float2(acc[m][nb][2] + bb.x, acc[m][nb][3] + bb.y);
        }
    }
}

// ============================================================================
// Causal flash attention, fp16 mma, REGISTER-RESIDENT P:
// the half2-packed QK^T C-fragments ARE the PV A-fragments (m16n8k16 layout
// identity), so P never touches smem — no stmatrix/ldmatrix for P, no
// syncwarp. f16x2 ex2 softmax; row sums via hadd2 trees + quad shuffles.
// Grid (32, 16), largest Q tile first.
// ============================================================================
#define STH 72   // halves; rows 144B apart -> LDSM conflict-free
#define SMEM_ATT ((128*STH + 2*64*STH + 2*64*STH) * (int)sizeof(__half))

__global__ __launch_bounds__(256, 2) void attn_mma_kernel()
{
    extern __shared__ __half smh[];
    __half* Ps  = smh;                   // 128 x STH (Q staging only)
    __half* Ks0 = Ps + 128*STH;
    __half* Vs0 = Ks0 + 2*64*STH;        // [d][j]

    const int tid  = threadIdx.x;
    const int w    = tid >> 5;
    const int lane = tid & 31;
    const int g    = lane >> 2;
    const int t    = lane & 3;
    const int bh   = blockIdx.y;
    const int it   = (int)gridDim.x - 1 - (int)blockIdx.x;

    const __half* qb = g_q  + (size_t)bh*S_*D_ + (size_t)it*128*D_;
    const __half* kb = g_k  + (size_t)bh*S_*D_;
    const __half* vb = g_vT + (size_t)bh*D_*S_;

    const uint32_t psm = (uint32_t)__cvta_generic_to_shared(Ps);
    const uint32_t ksm = (uint32_t)__cvta_generic_to_shared(Ks0);
    const uint32_t vsm = (uint32_t)__cvta_generic_to_shared(Vs0);

    const int qq = lane >> 3;
    const int rr = lane & 7;
    const int b_off = (((qq >> 1)*8 + rr)*STH + (qq & 1)*8) * 2;
    const int a_off = ((w*16 + (qq & 1)*8 + rr)*STH + (qq >> 1)*8) * 2;

    const int klr = tid >> 2;
    const int klc = (tid & 3) * 16;

    // prefetch KV tile 0
    {
        const __half* kr = kb + (size_t)klr*D_ + klc;
        const __half* vr = vb + (size_t)klr*S_ + klc;
        cp16h(&Ks0[klr*STH + klc],     kr);
        cp16h(&Ks0[klr*STH + klc + 8], kr + 8);
        cp16h(&Vs0[klr*STH + klc],     vr);
        cp16h(&Vs0[klr*STH + klc + 8], vr + 8);
        asm volatile("cp.async.commit_group;\n");
    }

    // stage Q, lift fragments
    {
        int lr = tid >> 1, lc = (tid & 1)*32;
        #pragma unroll
        for (int i = 0; i < 4; i++)
            *(float4*)&Ps[lr*STH + lc + i*8] = *(const float4*)&qb[lr*D_ + lc + i*8];
    }
    __syncthreads();

    const int row_a = w*16 + g;
    const int row_b = row_a + 8;
    const int gi_a  = it*128 + row_a;
    const int gi_b  = it*128 + row_b;

    uint32_t qf[4][4];
    #pragma unroll
    for (int kc = 0; kc < 4; kc++)
        ldsm_x4(qf[kc][0], qf[kc][1], qf[kc][2], qf[kc][3],
                psm + kc*32 + a_off);

    float oc[8][4];
    #pragma unroll
    for (int nb = 0; nb < 8; nb++)
        #pragma unroll
        for (int r = 0; r < 4; r++) oc[nb][r] = 0.f;
    float l_a = 0.f, l_b = 0.f;

    const int njt = 2*it + 2;

    for (int jt = 0; jt < njt; jt++) {
        const int buf = jt & 1;
        asm volatile("cp.async.wait_group 0;\n");
        __syncthreads();

        if (jt + 1 < njt) {
            const __half* kr = kb + (size_t)((jt+1)*64 + klr)*D_ + klc;
            const __half* vr = vb + (size_t)klr*S_ + (jt+1)*64 + klc;
            __half* Kd = Ks0 + (buf^1)*64*STH;
            __half* Vd = Vs0 + (buf^1)*64*STH;
            cp16h(&Kd[klr*STH + klc],     kr);
            cp16h(&Kd[klr*STH + klc + 8], kr + 8);
            cp16h(&Vd[klr*STH + klc],     vr);
            cp16h(&Vd[klr*STH + klc + 8], vr + 8);
            asm volatile("cp.async.commit_group;\n");
        }

        const uint32_t kbase = ksm + buf*(64*STH*2) + b_off;
        const uint32_t vbase = vsm + buf*(64*STH*2) + b_off;

        // ---- S = Q K^T ----
        float sc[8][4];
        #pragma unroll
        for (int nb = 0; nb < 8; nb++)
            #pragma unroll
            for (int r = 0; r < 4; r++) sc[nb][r] = 0.f;

        #pragma unroll
        for (int kc = 0; kc < 4; kc++) {
            #pragma unroll
            for (int nbp = 0; nbp < 4; nbp++) {
                uint32_t b0, b1, c0, c1;
                ldsm_x4(b0, b1, c0, c1, kbase + nbp*(16*STH*2) + kc*32);
                mma_f16(sc[2*nbp][0], sc[2*nbp][1], sc[2*nbp][2], sc[2*nbp][3],
                        qf[kc][0], qf[kc][1], qf[kc][2], qf[kc][3], b0, b1);
                mma_f16(sc[2*nbp+1][0], sc[2*nbp+1][1], sc[2*nbp+1][2], sc[2*nbp+1][3],
                        qf[kc][0], qf[kc][1], qf[kc][2], qf[kc][3], c0, c1);
            }
        }

        // ---- causal mask (-30: 2^-30 underflows half -> exactly 0) ----
        if (jt >= 2*it) {
            int jbase = jt*64;
            #pragma unroll
            for (int nb = 0; nb < 8; nb++) {
                int j0 = jbase + nb*8 + 2*t;
                if (j0     > gi_a) sc[nb][0] = -30.f;
                if (j0 + 1 > gi_a) sc[nb][1] = -30.f;
                if (j0     > gi_b) sc[nb][2] = -30.f;
                if (j0 + 1 > gi_b) sc[nb][3] = -30.f;
            }
        }

        // ---- softmax numerator: pack, ex2.f16x2 -> P stays in registers ----
        uint32_t ph0[8], ph1[8];
        #pragma unroll
        for (int nb = 0; nb < 8; nb++) {
            ph0[nb] = h2ex2(pack2(sc[nb][0], sc[nb][1]));
            ph1[nb] = h2ex2(pack2(sc[nb][2], sc[nb][3]));
        }

        // row sums: hadd2 tree, then fp32 quad reduction
        {
            __half2 ha = u2h(ph0[0]);
            __half2 hb = u2h(ph1[0]);
            #pragma unroll
            for (int nb = 1; nb < 8; nb++) {
                ha = __hadd2(ha, u2h(ph0[nb]));
                hb = __hadd2(hb, u2h(ph1[nb]));
            }
            float2 fa = __half22float2(ha);
            float2 fb = __half22float2(hb);
            float suma = fa.x + fa.y;
            float sumb = fb.x + fb.y;
            suma += __shfl_xor_sync(0xffffffffu, suma, 1);
            suma += __shfl_xor_sync(0xffffffffu, suma, 2);
            sumb += __shfl_xor_sync(0xffffffffu, sumb, 1);
            sumb += __shfl_xor_sync(0xffffffffu, sumb, 2);
            l_a += suma;
            l_b += sumb;
        }

        // ---- O += P V  (A fragments = ph0/ph1 directly; layout identity) ----
        #pragma unroll
        for (int kc = 0; kc < 4; kc++) {
            uint32_t a0 = ph0[2*kc], a1 = ph1[2*kc];
            uint32_t a2 = ph0[2*kc+1], a3 = ph1[2*kc+1];
            #pragma unroll
            for (int nbp = 0; nbp < 4; nbp++) {
                uint32_t b0, b1, c0, c1;
                ldsm_x4(b0, b1, c0, c1, vbase + nbp*(16*STH*2) + kc*32);
                mma_f16(oc[2*nbp][0], oc[2*nbp][1], oc[2*nbp][2], oc[2*nbp][3],
                        a0, a1, a2, a3, b0, b1);
                mma_f16(oc[2*nbp+1][0], oc[2*nbp+1][1], oc[2*nbp+1][2], oc[2*nbp+1][3],
                        a0, a1, a2, a3, c0, c1);
            }
        }
    }

    // ---- epilogue ----
    {
        float inva = 1.f / l_a, invb = 1.f / l_b;
        int b = bh >> 3, h = bh & 7;
        __half* da = g_att + (size_t)(b*S_ + gi_a)*DM_ + h*D_;
        __half* db = g_att + (size_t)(b*S_ + gi_b)*DM_ + h*D_;
        #pragma unroll
        for (int nb = 0; nb < 8; nb++) {
            *(__half2*)&da[nb*8 + 2*t] =
                __floats2half2_rn(oc[nb][0]*inva, oc[nb][1]*inva);
            *(__half2*)&db[nb*8 + 2*t] =
                __floats2half2_rn(oc[nb][2]*invb, oc[nb][3]*invb);
        }
    }
}

// ============================================================================
extern "C" void kernel_launch(void* const* d_in, const int* in_sizes, int n_in,
                              void* d_out, int out_size)
{
    const float* x  = (const float*)d_in[0];
    const float* Wq = (const float*)d_in[2];
    const float* bq = (const float*)d_in[3];
    const float* Wk = (const float*)d_in[4];
    const float* bk = (const float*)d_in[5];
    const float* Wv = (const float*)d_in[6];
    const float* bv = (const float*)d_in[7];
    const float* Wo = (const float*)d_in[8];
    const float* bo = (const float*)d_in[9];
    float* out = (float*)d_out;

    __half *wo, *att;
    cudaGetSymbolAddress((void**)&wo,  g_wo);
    cudaGetSymbolAddress((void**)&att, g_att);

    prep_kernel<<<5632, 256>>>(x, Wq, Wk, Wv, Wo);

    qkv_rope_kernel<<<dim3(12, ROWS_/128), 256>>>(bq, bk, bv);

    cudaFuncSetAttribute(attn_mma_kernel,
                         cudaFuncAttributeMaxDynamicSharedMemorySize, SMEM_ATT);
    attn_mma_kernel<<<dim3(S_/128, B_*H_), 256, SMEM_ATT>>>();

    gemm_f16_kernel<<<dim3(DM_/128, ROWS_/128), 256>>>(att, wo, bo, out,
                                                       ROWS_, DM_, DM_);
}

// round 13
// speedup vs baseline: 1.0797x; 1.0037x over previous
#include <cuda_runtime.h>
#include <cuda_fp16.h>
#include <math.h>
#include <stdint.h>

#define B_    2
#define H_    8
#define S_    4096
#define D_    64
#define DM_   512
#define ROWS_ (B_*S_)   // 8192

// ---- scratch (static __device__ arrays; no allocation allowed) ----
__device__ __half g_x [ROWS_*DM_];
__device__ __half g_wq[DM_*DM_];
__device__ __half g_wk[DM_*DM_];
__device__ __half g_wv[DM_*DM_];
__device__ __half g_wo[DM_*DM_];
__device__ __half g_q [B_*H_*S_*D_];   // [B,H,S,D] (Q pre-scaled 1/8*log2e)
__device__ __half g_k [B_*H_*S_*D_];   // [B,H,S,D]
__device__ __half g_vT[B_*H_*D_*S_];   // [B,H,D,S] (transposed)
__device__ __half g_att[ROWS_*DM_];    // attention out, [B,S,H*D]
__device__ float2 g_cs[S_*32];         // (cos, sin) per (s, d2)

__device__ __forceinline__ void cp16h(__half* s, const __half* g) {
    uint32_t sa = (uint32_t)__cvta_generic_to_shared(s);
    asm volatile("cp.async.cg.shared.global [%0], [%1], 16;\n" :: "r"(sa), "l"(g));
}

__device__ __forceinline__ void mma_f16(
    float& c0, float& c1, float& c2, float& c3,
    uint32_t a0, uint32_t a1, uint32_t a2, uint32_t a3,
    uint32_t b0, uint32_t b1)
{
    asm volatile(
        "mma.sync.aligned.m16n8k16.row.col.f32.f16.f16.f32 "
        "{%0,%1,%2,%3}, {%4,%5,%6,%7}, {%8,%9}, {%0,%1,%2,%3};"
        : "+f"(c0), "+f"(c1), "+f"(c2), "+f"(c3)
        : "r"(a0), "r"(a1), "r"(a2), "r"(a3), "r"(b0), "r"(b1));
}

__device__ __forceinline__ void ldsm_x4(
    uint32_t& r0, uint32_t& r1, uint32_t& r2, uint32_t& r3, uint32_t addr)
{
    asm volatile(
        "ldmatrix.sync.aligned.m8n8.x4.shared.b16 {%0,%1,%2,%3}, [%4];"
        : "=r"(r0), "=r"(r1), "=r"(r2), "=r"(r3) : "r"(addr));
}

__device__ __forceinline__ uint32_t pack2(float a, float b) {
    __half2 h = __floats2half2_rn(a, b);
    return *reinterpret_cast<uint32_t*>(&h);
}

__device__ __forceinline__ uint32_t h2ex2(uint32_t x) {
    uint32_t y;
    asm("ex2.approx.f16x2 %0, %1;" : "=r"(y) : "r"(x));
    return y;
}

__device__ __forceinline__ __half2 u2h(uint32_t x) {
    return *reinterpret_cast<__half2*>(&x);
}

// Tail-correct pipelined wait: stages issued so far = min(i+3, nk)
__device__ __forceinline__ void pipe_wait(int i, int nk) {
    if (i < nk - 2)       asm volatile("cp.async.wait_group 2;\n");
    else if (i == nk - 2) asm volatile("cp.async.wait_group 1;\n");
    else                  asm volatile("cp.async.wait_group 0;\n");
}

// ============================================================================
// One fused prep kernel: fp16-round x & weights + cos/sin table.
// ============================================================================
#define NW4 (DM_*DM_/4)
__global__ __launch_bounds__(256) void prep_kernel(
    const float* __restrict__ x,
    const float* __restrict__ wq, const float* __restrict__ wk,
    const float* __restrict__ wv, const float* __restrict__ wo)
{
    int bx = blockIdx.x;
    if (bx < 4096) {
        int i = bx*256 + threadIdx.x;
        float4 v = ((const float4*)x)[i];
        ((__half2*)g_x)[i*2]   = __floats2half2_rn(v.x, v.y);
        ((__half2*)g_x)[i*2+1] = __floats2half2_rn(v.z, v.w);
    } else if (bx < 5120) {
        int idx = (bx - 4096)*256 + threadIdx.x;
        int seg = idx >> 16;
        int i   = idx & (NW4 - 1);
        const float* src = seg == 0 ? wq : seg == 1 ? wk : seg == 2 ? wv : wo;
        __half* dst      = seg == 0 ? g_wq : seg == 1 ? g_wk : seg == 2 ? g_wv : g_wo;
        float4 v = ((const float4*)src)[i];
        ((__half2*)dst)[i*2]   = __floats2half2_rn(v.x, v.y);
        ((__half2*)dst)[i*2+1] = __floats2half2_rn(v.z, v.w);
    } else {
        int id = (bx - 5120)*256 + threadIdx.x;
        int d2 = id & 31, s = id >> 5;
        double invf = exp2(-(double)d2 * (13.287712379549449 / 32.0));
        double ph   = (double)s * invf;
        double n    = rint(ph * 0.15915494309189535);
        float  r    = (float)(ph - 6.283185307179586 * n);
        float sn, cs;
        sincosf(r, &sn, &cs);
        g_cs[id] = make_float2(cs, sn);
    }
}

// ============================================================================
// GEMM cores: 4-stage cp.async pipeline, dynamic smem, ldmatrix fragments.
// ============================================================================
#define GH 40            // halves; rows 80B -> LDSM phases all distinct mod 128
#define GSTG 4
#define GTILE (128*GH)   // halves per (A or B) stage
#define SMEM_GEMM (GSTG*GTILE*2*2)   // 81920 B

// ============================================================================
// Fused QKV GEMM + bias + RoPE + transpose; fp16 in/out.
// Q scaled by (1/8)*log2(e) so attention softmax can use ex2 directly.
// ============================================================================
__global__ __launch_bounds__(256, 2) void qkv_rope_kernel(
    const float* __restrict__ bq, const float* __restrict__ bk,
    const float* __restrict__ bv)
{
    extern __shared__ __half smg[];
    __half* As = smg;                    // GSTG x GTILE
    __half* Bs = smg + GSTG*GTILE;

    const int tid  = threadIdx.x;
    const int w    = tid >> 5;
    const int lane = tid & 31;
    const int g    = lane >> 2;
    const int t    = lane & 3;
    const int wm   = w >> 1;
    const int wn   = w & 1;
    const int bm   = blockIdx.y * 128;
    const int kind = blockIdx.x >> 2;
    const int bn   = (blockIdx.x & 3) * 128;
    const int K    = DM_;

    const __half* Wbase = kind == 0 ? g_wq : kind == 1 ? g_wk : g_wv;
    const float*  bias  = kind == 0 ? bq   : kind == 1 ? bk   : bv;

    const int lr  = tid >> 2;
    const int lch = (tid & 3) * 8;
    const __half* Ag = g_x + (size_t)(bm + lr) * K + lch;
    const __half* Wg = Wbase + (size_t)(bn + lr) * K + lch;
    const int so = lr*GH + lch;

    const uint32_t asmb = (uint32_t)__cvta_generic_to_shared(As);
    const uint32_t bsmb = (uint32_t)__cvta_generic_to_shared(Bs);
    const int qq = lane >> 3, rr = lane & 7;
    const int aoff = ((wm*32 + (qq & 1)*8 + rr)*GH + (qq >> 1)*8) * 2;
    const int boff = ((wn*64 + (qq >> 1)*8 + rr)*GH + (qq & 1)*8) * 2;

    float acc[2][8][4];
    #pragma unroll
    for (int m = 0; m < 2; m++)
        #pragma unroll
        for (int nb = 0; nb < 8; nb++)
            #pragma unroll
            for (int r = 0; r < 4; r++) acc[m][nb][r] = 0.f;

    const int nk = K / 32;   // 16
    // prologue: issue stages 0,1,2
    #pragma unroll
    for (int s = 0; s < GSTG - 1; s++) {
        int ko = s * 32;
        cp16h(&As[s*GTILE + so],         Ag + ko);
        cp16h(&As[s*GTILE + so + 64*GH], Ag + (size_t)64*K + ko);
        cp16h(&Bs[s*GTILE + so],         Wg + ko);
        cp16h(&Bs[s*GTILE + so + 64*GH], Wg + (size_t)64*K + ko);
        asm volatile("cp.async.commit_group;\n");
    }

    for (int i = 0; i < nk; i++) {
        pipe_wait(i, nk);
        __syncthreads();

        if (i + GSTG - 1 < nk) {
            int s  = (i + GSTG - 1) & (GSTG - 1);
            int ko = (i + GSTG - 1) * 32;
            cp16h(&As[s*GTILE + so],         Ag + ko);
            cp16h(&As[s*GTILE + so + 64*GH], Ag + (size_t)64*K + ko);
            cp16h(&Bs[s*GTILE + so],         Wg + ko);
            cp16h(&Bs[s*GTILE + so + 64*GH], Wg + (size_t)64*K + ko);
            asm volatile("cp.async.commit_group;\n");
        }

        const int buf = i & (GSTG - 1);
        const uint32_t Abase = asmb + buf*(GTILE*2) + aoff;
        const uint32_t Bbase = bsmb + buf*(GTILE*2) + boff;
        #pragma unroll
        for (int kc = 0; kc < 2; kc++) {
            uint32_t a[2][4];
            ldsm_x4(a[0][0], a[0][1], a[0][2], a[0][3], Abase + kc*32);
            ldsm_x4(a[1][0], a[1][1], a[1][2], a[1][3],
                    Abase + 16*GH*2 + kc*32);
            #pragma unroll
            for (int nbp = 0; nbp < 4; nbp++) {
                uint32_t b0, b1, c0, c1;
                ldsm_x4(b0, b1, c0, c1, Bbase + nbp*(16*GH*2) + kc*32);
                mma_f16(acc[0][2*nbp][0], acc[0][2*nbp][1],
                        acc[0][2*nbp][2], acc[0][2*nbp][3],
                        a[0][0], a[0][1], a[0][2], a[0][3], b0, b1);
                mma_f16(acc[1][2*nbp][0], acc[1][2*nbp][1],
                        acc[1][2*nbp][2], acc[1][2*nbp][3],
                        a[1][0], a[1][1], a[1][2], a[1][3], b0, b1);
                mma_f16(acc[0][2*nbp+1][0], acc[0][2*nbp+1][1],
                        acc[0][2*nbp+1][2], acc[0][2*nbp+1][3],
                        a[0][0], a[0][1], a[0][2], a[0][3], c0, c1);
                mma_f16(acc[1][2*nbp+1][0], acc[1][2*nbp+1][1],
                        acc[1][2*nbp+1][2], acc[1][2*nbp+1][3],
                        a[1][0], a[1][1], a[1][2], a[1][3], c0, c1);
            }
        }
    }

    const int head  = (bn + wn*64) >> 6;
    const int bcol  = bn + wn*64;
    const float qsc = (kind == 0) ? 0.125f * 1.4426950408889634f : 1.f;

    #pragma unroll
    for (int m = 0; m < 2; m++) {
        #pragma unroll
        for (int hh = 0; hh < 2; hh++) {
            int row = bm + wm*32 + m*16 + g + hh*8;
            int bb  = row >> 12;
            int ss  = row & (S_ - 1);
            #pragma unroll
            for (int nbl = 0; nbl < 4; nbl++) {
                int c = nbl*8 + 2*t;
                float lo0 = acc[m][nbl  ][hh*2+0] + bias[bcol + c];
                float lo1 = acc[m][nbl  ][hh*2+1] + bias[bcol + c + 1];
                float hi0 = acc[m][nbl+4][hh*2+0] + bias[bcol + c + 32];
                float hi1 = acc[m][nbl+4][hh*2+1] + bias[bcol + c + 33];
                if (kind == 2) {
                    __half* dv = g_vT + ((size_t)(bb*H_ + head)*D_)*S_ + ss;
                    dv[(size_t)(c     )*S_] = __float2half_rn(lo0);
                    dv[(size_t)(c +  1)*S_] = __float2half_rn(lo1);
                    dv[(size_t)(c + 32)*S_] = __float2half_rn(hi0);
                    dv[(size_t)(c + 33)*S_] = __float2half_rn(hi1);
                } else {
                    float2 cs0 = g_cs[ss*32 + c];
                    float2 cs1 = g_cs[ss*32 + c + 1];
                    float o_lo0 = (lo0*cs0.x - hi0*cs0.y) * qsc;
                    float o_hi0 = (hi0*cs0.x + lo0*cs0.y) * qsc;
                    float o_lo1 = (lo1*cs1.x - hi1*cs1.y) * qsc;
                    float o_hi1 = (hi1*cs1.x + lo1*cs1.y) * qsc;
                    __half* dst = (kind == 0 ? g_q : g_k)
                                + ((size_t)(bb*H_ + head)*S_ + ss)*D_;
                    *(__half2*)&dst[c]      = __floats2half2_rn(o_lo0, o_lo1);
                    *(__half2*)&dst[c + 32] = __floats2half2_rn(o_hi0, o_hi1);
                }
            }
        }
    }
}

// ============================================================================
// fp16 GEMM (out-projection), 4-stage pipeline, ldmatrix fragments.
// ============================================================================
__global__ __launch_bounds__(256, 2) void gemm_f16_kernel(
    const __half* __restrict__ A, const __half* __restrict__ W,
    const float* __restrict__ bias, float* __restrict__ C,
    int M, int N, int K)
{
    extern __shared__ __half smg[];
    __half* As = smg;
    __half* Bs = smg + GSTG*GTILE;

    const int tid  = threadIdx.x;
    const int w    = tid >> 5;
    const int lane = tid & 31;
    const int g    = lane >> 2;
    const int t    = lane & 3;
    const int wm   = w >> 1;
    const int wn   = w & 1;
    const int bm   = blockIdx.y * 128;
    const int bn   = blockIdx.x * 128;

    const int lr  = tid >> 2;
    const int lch = (tid & 3) * 8;
    const __half* Ag = A + (size_t)(bm + lr) * K + lch;
    const __half* Wg = W + (size_t)(bn + lr) * K + lch;
    const int so = lr*GH + lch;

    const uint32_t asmb = (uint32_t)__cvta_generic_to_shared(As);
    const uint32_t bsmb = (uint32_t)__cvta_generic_to_shared(Bs);
    const int qq = lane >> 3, rr = lane & 7;
    const int aoff = ((wm*32 + (qq & 1)*8 + rr)*GH + (qq >> 1)*8) * 2;
    const int boff = ((wn*64 + (qq >> 1)*8 + rr)*GH + (qq & 1)*8) * 2;

    float acc[2][8][4];
    #pragma unroll
    for (int m = 0; m < 2; m++)
        #pragma unroll
        for (int nb = 0; nb < 8; nb++)
            #pragma unroll
            for (int r = 0; r < 4; r++) acc[m][nb][r] = 0.f;

    const int nk = K / 32;
    #pragma unroll
    for (int s = 0; s < GSTG - 1; s++) {
        int ko = s * 32;
        cp16h(&As[s*GTILE + so],         Ag + ko);
        cp16h(&As[s*GTILE + so + 64*GH], Ag + (size_t)64*K + ko);
        cp16h(&Bs[s*GTILE + so],         Wg + ko);
        cp16h(&Bs[s*GTILE + so + 64*GH], Wg + (size_t)64*K + ko);
        asm volatile("cp.async.commit_group;\n");
    }

    for (int i = 0; i < nk; i++) {
        pipe_wait(i, nk);
        __syncthreads();

        if (i + GSTG - 1 < nk) {
            int s  = (i + GSTG - 1) & (GSTG - 1);
            int ko = (i + GSTG - 1) * 32;
            cp16h(&As[s*GTILE + so],         Ag + ko);
            cp16h(&As[s*GTILE + so + 64*GH], Ag + (size_t)64*K + ko);
            cp16h(&Bs[s*GTILE + so],         Wg + ko);
            cp16h(&Bs[s*GTILE + so + 64*GH], Wg + (size_t)64*K + ko);
            asm volatile("cp.async.commit_group;\n");
        }

        const int buf = i & (GSTG - 1);
        const uint32_t Abase = asmb + buf*(GTILE*2) + aoff;
        const uint32_t Bbase = bsmb + buf*(GTILE*2) + boff;
        #pragma unroll
        for (int kc = 0; kc < 2; kc++) {
            uint32_t a[2][4];
            ldsm_x4(a[0][0], a[0][1], a[0][2], a[0][3], Abase + kc*32);
            ldsm_x4(a[1][0], a[1][1], a[1][2], a[1][3],
                    Abase + 16*GH*2 + kc*32);
            #pragma unroll
            for (int nbp = 0; nbp < 4; nbp++) {
                uint32_t b0, b1, c0, c1;
                ldsm_x4(b0, b1, c0, c1, Bbase + nbp*(16*GH*2) + kc*32);
                mma_f16(acc[0][2*nbp][0], acc[0][2*nbp][1],
                        acc[0][2*nbp][2], acc[0][2*nbp][3],
                        a[0][0], a[0][1], a[0][2], a[0][3], b0, b1);
                mma_f16(acc[1][2*nbp][0], acc[1][2*nbp][1],
                        acc[1][2*nbp][2], acc[1][2*nbp][3],
                        a[1][0], a[1][1], a[1][2], a[1][3], b0, b1);
                mma_f16(acc[0][2*nbp+1][0], acc[0][2*nbp+1][1],
                        acc[0][2*nbp+1][2], acc[0][2*nbp+1][3],
                        a[0][0], a[0][1], a[0][2], a[0][3], c0, c1);
                mma_f16(acc[1][2*nbp+1][0], acc[1][2*nbp+1][1],
                        acc[1][2*nbp+1][2], acc[1][2*nbp+1][3],
                        a[1][0], a[1][1], a[1][2], a[1][3], c0, c1);
            }
        }
    }

    #pragma unroll
    for (int m = 0; m < 2; m++) {
        int row = bm + wm*32 + m*16 + g;
        #pragma unroll
        for (int nb = 0; nb < 8; nb++) {
            int n = bn + wn*64 + nb*8 + 2*t;
            float2 bb = *(const float2*)&bias[n];
            *(float2*)&C[(size_t)row*N + n] =
                make_float2(acc[m][nb][0] + bb.x, acc[m][nb][1] + bb.y);
            *(float2*)&C[(size_t)(row+8)*N + n] =
                make_float2(acc[m][nb][2] + bb.x, acc[m][nb][3] + bb.y);
        }
    }
}

// ============================================================================
// Causal flash attention, fp16 mma, register-resident P.  (unchanged R12)
// ============================================================================
#define STH 72   // halves; rows 144B apart -> LDSM conflict-free
#define SMEM_ATT ((128*STH + 2*64*STH + 2*64*STH) * (int)sizeof(__half))

__global__ __launch_bounds__(256, 2) void attn_mma_kernel()
{
    extern __shared__ __half smh[];
    __half* Ps  = smh;                   // 128 x STH (Q staging only)
    __half* Ks0 = Ps + 128*STH;
    __half* Vs0 = Ks0 + 2*64*STH;        // [d][j]

    const int tid  = threadIdx.x;
    const int w    = tid >> 5;
    const int lane = tid & 31;
    const int g    = lane >> 2;
    const int t    = lane & 3;
    const int bh   = blockIdx.y;
    const int it   = (int)gridDim.x - 1 - (int)blockIdx.x;

    const __half* qb = g_q  + (size_t)bh*S_*D_ + (size_t)it*128*D_;
    const __half* kb = g_k  + (size_t)bh*S_*D_;
    const __half* vb = g_vT + (size_t)bh*D_*S_;

    const uint32_t psm = (uint32_t)__cvta_generic_to_shared(Ps);
    const uint32_t ksm = (uint32_t)__cvta_generic_to_shared(Ks0);
    const uint32_t vsm = (uint32_t)__cvta_generic_to_shared(Vs0);

    const int qq = lane >> 3;
    const int rr = lane & 7;
    const int b_off = (((qq >> 1)*8 + rr)*STH + (qq & 1)*8) * 2;
    const int a_off = ((w*16 + (qq & 1)*8 + rr)*STH + (qq >> 1)*8) * 2;

    const int klr = tid >> 2;
    const int klc = (tid & 3) * 16;

    {
        const __half* kr = kb + (size_t)klr*D_ + klc;
        const __half* vr = vb + (size_t)klr*S_ + klc;
        cp16h(&Ks0[klr*STH + klc],     kr);
        cp16h(&Ks0[klr*STH + klc + 8], kr + 8);
        cp16h(&Vs0[klr*STH + klc],     vr);
        cp16h(&Vs0[klr*STH + klc + 8], vr + 8);
        asm volatile("cp.async.commit_group;\n");
    }

    {
        int lr = tid >> 1, lc = (tid & 1)*32;
        #pragma unroll
        for (int i = 0; i < 4; i++)
            *(float4*)&Ps[lr*STH + lc + i*8] = *(const float4*)&qb[lr*D_ + lc + i*8];
    }
    __syncthreads();

    const int row_a = w*16 + g;
    const int row_b = row_a + 8;
    const int gi_a  = it*128 + row_a;
    const int gi_b  = it*128 + row_b;

    uint32_t qf[4][4];
    #pragma unroll
    for (int kc = 0; kc < 4; kc++)
        ldsm_x4(qf[kc][0], qf[kc][1], qf[kc][2], qf[kc][3],
                psm + kc*32 + a_off);

    float oc[8][4];
    #pragma unroll
    for (int nb = 0; nb < 8; nb++)
        #pragma unroll
        for (int r = 0; r < 4; r++) oc[nb][r] = 0.f;
    float l_a = 0.f, l_b = 0.f;

    const int njt = 2*it + 2;

    for (int jt = 0; jt < njt; jt++) {
        const int buf = jt & 1;
        asm volatile("cp.async.wait_group 0;\n");
        __syncthreads();

        if (jt + 1 < njt) {
            const __half* kr = kb + (size_t)((jt+1)*64 + klr)*D_ + klc;
            const __half* vr = vb + (size_t)klr*S_ + (jt+1)*64 + klc;
            __half* Kd = Ks0 + (buf^1)*64*STH;
            __half* Vd = Vs0 + (buf^1)*64*STH;
            cp16h(&Kd[klr*STH + klc],     kr);
            cp16h(&Kd[klr*STH + klc + 8], kr + 8);
            cp16h(&Vd[klr*STH + klc],     vr);
            cp16h(&Vd[klr*STH + klc + 8], vr + 8);
            asm volatile("cp.async.commit_group;\n");
        }

        const uint32_t kbase = ksm + buf*(64*STH*2) + b_off;
        const uint32_t vbase = vsm + buf*(64*STH*2) + b_off;

        float sc[8][4];
        #pragma unroll
        for (int nb = 0; nb < 8; nb++)
            #pragma unroll
            for (int r = 0; r < 4; r++) sc[nb][r] = 0.f;

        #pragma unroll
        for (int kc = 0; kc < 4; kc++) {
            #pragma unroll
            for (int nbp = 0; nbp < 4; nbp++) {
                uint32_t b0, b1, c0, c1;
                ldsm_x4(b0, b1, c0, c1, kbase + nbp*(16*STH*2) + kc*32);
                mma_f16(sc[2*nbp][0], sc[2*nbp][1], sc[2*nbp][2], sc[2*nbp][3],
                        qf[kc][0], qf[kc][1], qf[kc][2], qf[kc][3], b0, b1);
                mma_f16(sc[2*nbp+1][0], sc[2*nbp+1][1], sc[2*nbp+1][2], sc[2*nbp+1][3],
                        qf[kc][0], qf[kc][1], qf[kc][2], qf[kc][3], c0, c1);
            }
        }

        if (jt >= 2*it) {
            int jbase = jt*64;
            #pragma unroll
            for (int nb = 0; nb < 8; nb++) {
                int j0 = jbase + nb*8 + 2*t;
                if (j0     > gi_a) sc[nb][0] = -30.f;
                if (j0 + 1 > gi_a) sc[nb][1] = -30.f;
                if (j0     > gi_b) sc[nb][2] = -30.f;
                if (j0 + 1 > gi_b) sc[nb][3] = -30.f;
            }
        }

        uint32_t ph0[8], ph1[8];
        #pragma unroll
        for (int nb = 0; nb < 8; nb++) {
            ph0[nb] = h2ex2(pack2(sc[nb][0], sc[nb][1]));
            ph1[nb] = h2ex2(pack2(sc[nb][2], sc[nb][3]));
        }

        {
            __half2 ha = u2h(ph0[0]);
            __half2 hb = u2h(ph1[0]);
            #pragma unroll
            for (int nb = 1; nb < 8; nb++) {
                ha = __hadd2(ha, u2h(ph0[nb]));
                hb = __hadd2(hb, u2h(ph1[nb]));
            }
            float2 fa = __half22float2(ha);
            float2 fb = __half22float2(hb);
            float suma = fa.x + fa.y;
            float sumb = fb.x + fb.y;
            suma += __shfl_xor_sync(0xffffffffu, suma, 1);
            suma += __shfl_xor_sync(0xffffffffu, suma, 2);
            sumb += __shfl_xor_sync(0xffffffffu, sumb, 1);
            sumb += __shfl_xor_sync(0xffffffffu, sumb, 2);
            l_a += suma;
            l_b += sumb;
        }

        #pragma unroll
        for (int kc = 0; kc < 4; kc++) {
            uint32_t a0 = ph0[2*kc], a1 = ph1[2*kc];
            uint32_t a2 = ph0[2*kc+1], a3 = ph1[2*kc+1];
            #pragma unroll
            for (int nbp = 0; nbp < 4; nbp++) {
                uint32_t b0, b1, c0, c1;
                ldsm_x4(b0, b1, c0, c1, vbase + nbp*(16*STH*2) + kc*32);
                mma_f16(oc[2*nbp][0], oc[2*nbp][1], oc[2*nbp][2], oc[2*nbp][3],
                        a0, a1, a2, a3, b0, b1);
                mma_f16(oc[2*nbp+1][0], oc[2*nbp+1][1], oc[2*nbp+1][2], oc[2*nbp+1][3],
                        a0, a1, a2, a3, c0, c1);
            }
        }
    }

    {
        float inva = 1.f / l_a, invb = 1.f / l_b;
        int b = bh >> 3, h = bh & 7;
        __half* da = g_att + (size_t)(b*S_ + gi_a)*DM_ + h*D_;
        __half* db = g_att + (size_t)(b*S_ + gi_b)*DM_ + h*D_;
        #pragma unroll
        for (int nb = 0; nb < 8; nb++) {
            *(__half2*)&da[nb*8 + 2*t] =
                __floats2half2_rn(oc[nb][0]*inva, oc[nb][1]*inva);
            *(__half2*)&db[nb*8 + 2*t] =
                __floats2half2_rn(oc[nb][2]*invb, oc[nb][3]*invb);
        }
    }
}

// ============================================================================
extern "C" void kernel_launch(void* const* d_in, const int* in_sizes, int n_in,
                              void* d_out, int out_size)
{
    const float* x  = (const float*)d_in[0];
    const float* Wq = (const float*)d_in[2];
    const float* bq = (const float*)d_in[3];
    const float* Wk = (const float*)d_in[4];
    const float* bk = (const float*)d_in[5];
    const float* Wv = (const float*)d_in[6];
    const float* bv = (const float*)d_in[7];
    const float* Wo = (const float*)d_in[8];
    const float* bo = (const float*)d_in[9];
    float* out = (float*)d_out;

    __half *wo, *att;
    cudaGetSymbolAddress((void**)&wo,  g_wo);
    cudaGetSymbolAddress((void**)&att, g_att);

    prep_kernel<<<5632, 256>>>(x, Wq, Wk, Wv, Wo);

    cudaFuncSetAttribute(qkv_rope_kernel,
                         cudaFuncAttributeMaxDynamicSharedMemorySize, SMEM_GEMM);
    qkv_rope_kernel<<<dim3(12, ROWS_/128), 256, SMEM_GEMM>>>(bq, bk, bv);

    cudaFuncSetAttribute(attn_mma_kernel,
                         cudaFuncAttributeMaxDynamicSharedMemorySize, SMEM_ATT);
    attn_mma_kernel<<<dim3(S_/128, B_*H_), 256, SMEM_ATT>>>();

    cudaFuncSetAttribute(gemm_f16_kernel,
                         cudaFuncAttributeMaxDynamicSharedMemorySize, SMEM_GEMM);
    gemm_f16_kernel<<<dim3(DM_/128, ROWS_/128), 256, SMEM_GEMM>>>(
        att, wo, bo, out, ROWS_, DM_, DM_);
}

// round 15
// speedup vs baseline: 1.1255x; 1.0424x over previous
#include <cuda_runtime.h>
#include <cuda_fp16.h>
#include <math.h>
#include <stdint.h>

#define B_    2
#define H_    8
#define S_    4096
#define D_    64
#define DM_   512
#define ROWS_ (B_*S_)   // 8192

// ---- scratch (static __device__ arrays; no allocation allowed) ----
__device__ __half g_x [ROWS_*DM_];
__device__ __half g_wq[DM_*DM_];
__device__ __half g_wk[DM_*DM_];
__device__ __half g_wv[DM_*DM_];
__device__ __half g_wo[DM_*DM_];
__device__ __half g_q [B_*H_*S_*D_];   // [B,H,S,D] (Q pre-scaled 1/8*log2e)
__device__ __half g_k [B_*H_*S_*D_];   // [B,H,S,D]
__device__ __half g_vT[B_*H_*D_*S_];   // [B,H,D,S] (transposed)
__device__ __half g_att[ROWS_*DM_];    // attention out, [B,S,H*D]
__device__ float2 g_cs[S_*32];         // (cos, sin) per (s, d2)

__device__ __forceinline__ void cp16h(__half* s, const __half* g) {
    uint32_t sa = (uint32_t)__cvta_generic_to_shared(s);
    asm volatile("cp.async.cg.shared.global [%0], [%1], 16;\n" :: "r"(sa), "l"(g));
}

// fp32-accumulator mma (used for GEMMs and PV)
__device__ __forceinline__ void mma_f16(
    float& c0, float& c1, float& c2, float& c3,
    uint32_t a0, uint32_t a1, uint32_t a2, uint32_t a3,
    uint32_t b0, uint32_t b1)
{
    asm volatile(
        "mma.sync.aligned.m16n8k16.row.col.f32.f16.f16.f32 "
        "{%0,%1,%2,%3}, {%4,%5,%6,%7}, {%8,%9}, {%0,%1,%2,%3};"
        : "+f"(c0), "+f"(c1), "+f"(c2), "+f"(c3)
        : "r"(a0), "r"(a1), "r"(a2), "r"(a3), "r"(b0), "r"(b1));
}

// fp16-accumulator mma (2x rate) — used for QK^T; C = packed half2 pairs
__device__ __forceinline__ void mma_f16h(
    uint32_t& c0, uint32_t& c1,
    uint32_t a0, uint32_t a1, uint32_t a2, uint32_t a3,
    uint32_t b0, uint32_t b1)
{
    asm volatile(
        "mma.sync.aligned.m16n8k16.row.col.f16.f16.f16.f16 "
        "{%0,%1}, {%2,%3,%4,%5}, {%6,%7}, {%0,%1};"
        : "+r"(c0), "+r"(c1)
        : "r"(a0), "r"(a1), "r"(a2), "r"(a3), "r"(b0), "r"(b1));
}

__device__ __forceinline__ void ldsm_x4(
    uint32_t& r0, uint32_t& r1, uint32_t& r2, uint32_t& r3, uint32_t addr)
{
    asm volatile(
        "ldmatrix.sync.aligned.m8n8.x4.shared.b16 {%0,%1,%2,%3}, [%4];"
        : "=r"(r0), "=r"(r1), "=r"(r2), "=r"(r3) : "r"(addr));
}

__device__ __forceinline__ uint32_t h2ex2(uint32_t x) {
    uint32_t y;
    asm("ex2.approx.f16x2 %0, %1;" : "=r"(y) : "r"(x));
    return y;
}

__device__ __forceinline__ __half2 u2h(uint32_t x) {
    return *reinterpret_cast<__half2*>(&x);
}

// Tail-correct pipelined wait: stages issued so far = min(i+3, nk)
__device__ __forceinline__ void pipe_wait(int i, int nk) {
    if (i < nk - 2)       asm volatile("cp.async.wait_group 2;\n");
    else if (i == nk - 2) asm volatile("cp.async.wait_group 1;\n");
    else                  asm volatile("cp.async.wait_group 0;\n");
}

// ============================================================================
// One fused prep kernel: fp16-round x & weights + cos/sin table.
// ============================================================================
#define NW4 (DM_*DM_/4)
__global__ __launch_bounds__(256) void prep_kernel(
    const float* __restrict__ x,
    const float* __restrict__ wq, const float* __restrict__ wk,
    const float* __restrict__ wv, const float* __restrict__ wo)
{
    int bx = blockIdx.x;
    if (bx < 4096) {
        int i = bx*256 + threadIdx.x;
        float4 v = ((const float4*)x)[i];
        ((__half2*)g_x)[i*2]   = __floats2half2_rn(v.x, v.y);
        ((__half2*)g_x)[i*2+1] = __floats2half2_rn(v.z, v.w);
    } else if (bx < 5120) {
        int idx = (bx - 4096)*256 + threadIdx.x;
        int seg = idx >> 16;
        int i   = idx & (NW4 - 1);
        const float* src = seg == 0 ? wq : seg == 1 ? wk : seg == 2 ? wv : wo;
        __half* dst      = seg == 0 ? g_wq : seg == 1 ? g_wk : seg == 2 ? g_wv : g_wo;
        float4 v = ((const float4*)src)[i];
        ((__half2*)dst)[i*2]   = __floats2half2_rn(v.x, v.y);
        ((__half2*)dst)[i*2+1] = __floats2half2_rn(v.z, v.w);
    } else {
        int id = (bx - 5120)*256 + threadIdx.x;
        int d2 = id & 31, s = id >> 5;
        double invf = exp2(-(double)d2 * (13.287712379549449 / 32.0));
        double ph   = (double)s * invf;
        double n    = rint(ph * 0.15915494309189535);
        float  r    = (float)(ph - 6.283185307179586 * n);
        float sn, cs;
        sincosf(r, &sn, &cs);
        g_cs[id] = make_float2(cs, sn);
    }
}

// ============================================================================
// GEMM cores: 4-stage cp.async pipeline, dynamic smem, ldmatrix fragments.
// ============================================================================
#define GH 40            // halves; rows 80B -> LDSM phases all distinct mod 128
#define GSTG 4
#define GTILE (128*GH)   // halves per (A or B) stage
#define SMEM_GEMM (GSTG*GTILE*2*2)   // 81920 B

// ============================================================================
// Fused QKV GEMM + bias + RoPE + transpose; fp16 in/out.
// Q scaled by (1/8)*log2(e) so attention softmax can use ex2 directly.
// ============================================================================
__global__ __launch_bounds__(256, 2) void qkv_rope_kernel(
    const float* __restrict__ bq, const float* __restrict__ bk,
    const float* __restrict__ bv)
{
    extern __shared__ __half smg[];
    __half* As = smg;                    // GSTG x GTILE
    __half* Bs = smg + GSTG*GTILE;

    const int tid  = threadIdx.x;
    const int w    = tid >> 5;
    const int lane = tid & 31;
    const int g    = lane >> 2;
    const int t    = lane & 3;
    const int wm   = w >> 1;
    const int wn   = w & 1;
    const int bm   = blockIdx.y * 128;
    const int kind = blockIdx.x >> 2;
    const int bn   = (blockIdx.x & 3) * 128;
    const int K    = DM_;

    const __half* Wbase = kind == 0 ? g_wq : kind == 1 ? g_wk : g_wv;
    const float*  bias  = kind == 0 ? bq   : kind == 1 ? bk   : bv;

    const int lr  = tid >> 2;
    const int lch = (tid & 3) * 8;
    const __half* Ag = g_x + (size_t)(bm + lr) * K + lch;
    const __half* Wg = Wbase + (size_t)(bn + lr) * K + lch;
    const int so = lr*GH + lch;

    const uint32_t asmb = (uint32_t)__cvta_generic_to_shared(As);
    const uint32_t bsmb = (uint32_t)__cvta_generic_to_shared(Bs);
    const int qq = lane >> 3, rr = lane & 7;
    const int aoff = ((wm*32 + (qq & 1)*8 + rr)*GH + (qq >> 1)*8) * 2;
    const int boff = ((wn*64 + (qq >> 1)*8 + rr)*GH + (qq & 1)*8) * 2;

    float acc[2][8][4];
    #pragma unroll
    for (int m = 0; m < 2; m++)
        #pragma unroll
        for (int nb = 0; nb < 8; nb++)
            #pragma unroll
            for (int r = 0; r < 4; r++) acc[m][nb][r] = 0.f;

    const int nk = K / 32;   // 16
    #pragma unroll
    for (int s = 0; s < GSTG - 1; s++) {
        int ko = s * 32;
        cp16h(&As[s*GTILE + so],         Ag + ko);
        cp16h(&As[s*GTILE + so + 64*GH], Ag + (size_t)64*K + ko);
        cp16h(&Bs[s*GTILE + so],         Wg + ko);
        cp16h(&Bs[s*GTILE + so + 64*GH], Wg + (size_t)64*K + ko);
        asm volatile("cp.async.commit_group;\n");
    }

    for (int i = 0; i < nk; i++) {
        pipe_wait(i, nk);
        __syncthreads();

        if (i + GSTG - 1 < nk) {
            int s  = (i + GSTG - 1) & (GSTG - 1);
            int ko = (i + GSTG - 1) * 32;
            cp16h(&As[s*GTILE + so],         Ag + ko);
            cp16h(&As[s*GTILE + so + 64*GH], Ag + (size_t)64*K + ko);
            cp16h(&Bs[s*GTILE + so],         Wg + ko);
            cp16h(&Bs[s*GTILE + so + 64*GH], Wg + (size_t)64*K + ko);
            asm volatile("cp.async.commit_group;\n");
        }

        const int buf = i & (GSTG - 1);
        const uint32_t Abase = asmb + buf*(GTILE*2) + aoff;
        const uint32_t Bbase = bsmb + buf*(GTILE*2) + boff;
        #pragma unroll
        for (int kc = 0; kc < 2; kc++) {
            uint32_t a[2][4];
            ldsm_x4(a[0][0], a[0][1], a[0][2], a[0][3], Abase + kc*32);
            ldsm_x4(a[1][0], a[1][1], a[1][2], a[1][3],
                    Abase + 16*GH*2 + kc*32);
            #pragma unroll
            for (int nbp = 0; nbp < 4; nbp++) {
                uint32_t b0, b1, c0, c1;
                ldsm_x4(b0, b1, c0, c1, Bbase + nbp*(16*GH*2) + kc*32);
                mma_f16(acc[0][2*nbp][0], acc[0][2*nbp][1],
                        acc[0][2*nbp][2], acc[0][2*nbp][3],
                        a[0][0], a[0][1], a[0][2], a[0][3], b0, b1);
                mma_f16(acc[1][2*nbp][0], acc[1][2*nbp][1],
                        acc[1][2*nbp][2], acc[1][2*nbp][3],
                        a[1][0], a[1][1], a[1][2], a[1][3], b0, b1);
                mma_f16(acc[0][2*nbp+1][0], acc[0][2*nbp+1][1],
                        acc[0][2*nbp+1][2], acc[0][2*nbp+1][3],
                        a[0][0], a[0][1], a[0][2], a[0][3], c0, c1);
                mma_f16(acc[1][2*nbp+1][0], acc[1][2*nbp+1][1],
                        acc[1][2*nbp+1][2], acc[1][2*nbp+1][3],
                        a[1][0], a[1][1], a[1][2], a[1][3], c0, c1);
            }
        }
    }

    const int head  = (bn + wn*64) >> 6;
    const int bcol  = bn + wn*64;
    const float qsc = (kind == 0) ? 0.125f * 1.4426950408889634f : 1.f;

    #pragma unroll
    for (int m = 0; m < 2; m++) {
        #pragma unroll
        for (int hh = 0; hh < 2; hh++) {
            int row = bm + wm*32 + m*16 + g + hh*8;
            int bb  = row >> 12;
            int ss  = row & (S_ - 1);
            #pragma unroll
            for (int nbl = 0; nbl < 4; nbl++) {
                int c = nbl*8 + 2*t;
                float lo0 = acc[m][nbl  ][hh*2+0] + bias[bcol + c];
                float lo1 = acc[m][nbl  ][hh*2+1] + bias[bcol + c + 1];
                float hi0 = acc[m][nbl+4][hh*2+0] + bias[bcol + c + 32];
                float hi1 = acc[m][nbl+4][hh*2+1] + bias[bcol + c + 33];
                if (kind == 2) {
                    __half* dv = g_vT + ((size_t)(bb*H_ + head)*D_)*S_ + ss;
                    dv[(size_t)(c     )*S_] = __float2half_rn(lo0);
                    dv[(size_t)(c +  1)*S_] = __float2half_rn(lo1);
                    dv[(size_t)(c + 32)*S_] = __float2half_rn(hi0);
                    dv[(size_t)(c + 33)*S_] = __float2half_rn(hi1);
                } else {
                    float2 cs0 = g_cs[ss*32 + c];
                    float2 cs1 = g_cs[ss*32 + c + 1];
                    float o_lo0 = (lo0*cs0.x - hi0*cs0.y) * qsc;
                    float o_hi0 = (hi0*cs0.x + lo0*cs0.y) * qsc;
                    float o_lo1 = (lo1*cs1.x - hi1*cs1.y) * qsc;
                    float o_hi1 = (hi1*cs1.x + lo1*cs1.y) * qsc;
                    __half* dst = (kind == 0 ? g_q : g_k)
                                + ((size_t)(bb*H_ + head)*S_ + ss)*D_;
                    *(__half2*)&dst[c]      = __floats2half2_rn(o_lo0, o_lo1);
                    *(__half2*)&dst[c + 32] = __floats2half2_rn(o_hi0, o_hi1);
                }
            }
        }
    }
}

// ============================================================================
// fp16 GEMM (out-projection), 4-stage pipeline, ldmatrix fragments.
// ============================================================================
__global__ __launch_bounds__(256, 2) void gemm_f16_kernel(
    const __half* __restrict__ A, const __half* __restrict__ W,
    const float* __restrict__ bias, float* __restrict__ C,
    int M, int N, int K)
{
    extern __shared__ __half smg[];
    __half* As = smg;
    __half* Bs = smg + GSTG*GTILE;

    const int tid  = threadIdx.x;
    const int w    = tid >> 5;
    const int lane = tid & 31;
    const int g    = lane >> 2;
    const int t    = lane & 3;
    const int wm   = w >> 1;
    const int wn   = w & 1;
    const int bm   = blockIdx.y * 128;
    const int bn   = blockIdx.x * 128;

    const int lr  = tid >> 2;
    const int lch = (tid & 3) * 8;
    const __half* Ag = A + (size_t)(bm + lr) * K + lch;
    const __half* Wg = W + (size_t)(bn + lr) * K + lch;
    const int so = lr*GH + lch;

    const uint32_t asmb = (uint32_t)__cvta_generic_to_shared(As);
    const uint32_t bsmb = (uint32_t)__cvta_generic_to_shared(Bs);
    const int qq = lane >> 3, rr = lane & 7;
    const int aoff = ((wm*32 + (qq & 1)*8 + rr)*GH + (qq >> 1)*8) * 2;
    const int boff = ((wn*64 + (qq >> 1)*8 + rr)*GH + (qq & 1)*8) * 2;

    float acc[2][8][4];
    #pragma unroll
    for (int m = 0; m < 2; m++)
        #pragma unroll
        for (int nb = 0; nb < 8; nb++)
            #pragma unroll
            for (int r = 0; r < 4; r++) acc[m][nb][r] = 0.f;

    const int nk = K / 32;
    #pragma unroll
    for (int s = 0; s < GSTG - 1; s++) {
        int ko = s * 32;
        cp16h(&As[s*GTILE + so],         Ag + ko);
        cp16h(&As[s*GTILE + so + 64*GH], Ag + (size_t)64*K + ko);
        cp16h(&Bs[s*GTILE + so],         Wg + ko);
        cp16h(&Bs[s*GTILE + so + 64*GH], Wg + (size_t)64*K + ko);
        asm volatile("cp.async.commit_group;\n");
    }

    for (int i = 0; i < nk; i++) {
        pipe_wait(i, nk);
        __syncthreads();

        if (i + GSTG - 1 < nk) {
            int s  = (i + GSTG - 1) & (GSTG - 1);
            int ko = (i + GSTG - 1) * 32;
            cp16h(&As[s*GTILE + so],         Ag + ko);
            cp16h(&As[s*GTILE + so + 64*GH], Ag + (size_t)64*K + ko);
            cp16h(&Bs[s*GTILE + so],         Wg + ko);
            cp16h(&Bs[s*GTILE + so + 64*GH], Wg + (size_t)64*K + ko);
            asm volatile("cp.async.commit_group;\n");
        }

        const int buf = i & (GSTG - 1);
        const uint32_t Abase = asmb + buf*(GTILE*2) + aoff;
        const uint32_t Bbase = bsmb + buf*(GTILE*2) + boff;
        #pragma unroll
        for (int kc = 0; kc < 2; kc++) {
            uint32_t a[2][4];
            ldsm_x4(a[0][0], a[0][1], a[0][2], a[0][3], Abase + kc*32);
            ldsm_x4(a[1][0], a[1][1], a[1][2], a[1][3],
                    Abase + 16*GH*2 + kc*32);
            #pragma unroll
            for (int nbp = 0; nbp < 4; nbp++) {
                uint32_t b0, b1, c0, c1;
                ldsm_x4(b0, b1, c0, c1, Bbase + nbp*(16*GH*2) + kc*32);
                mma_f16(acc[0][2*nbp][0], acc[0][2*nbp][1],
                        acc[0][2*nbp][2], acc[0][2*nbp][3],
                        a[0][0], a[0][1], a[0][2], a[0][3], b0, b1);
                mma_f16(acc[1][2*nbp][0], acc[1][2*nbp][1],
                        acc[1][2*nbp][2], acc[1][2*nbp][3],
                        a[1][0], a[1][1], a[1][2], a[1][3], b0, b1);
                mma_f16(acc[0][2*nbp+1][0], acc[0][2*nbp+1][1],
                        acc[0][2*nbp+1][2], acc[0][2*nbp+1][3],
                        a[0][0], a[0][1], a[0][2], a[0][3], c0, c1);
                mma_f16(acc[1][2*nbp+1][0], acc[1][2*nbp+1][1],
                        acc[1][2*nbp+1][2], acc[1][2*nbp+1][3],
                        a[1][0], a[1][1], a[1][2], a[1][3], c0, c1);
            }
        }
    }

    #pragma unroll
    for (int m = 0; m < 2; m++) {
        int row = bm + wm*32 + m*16 + g;
        #pragma unroll
        for (int nb = 0; nb < 8; nb++) {
            int n = bn + wn*64 + nb*8 + 2*t;
            float2 bb = *(const float2*)&bias[n];
            *(float2*)&C[(size_t)row*N + n] =
                make_float2(acc[m][nb][0] + bb.x, acc[m][nb][1] + bb.y);
            *(float2*)&C[(size_t)(row+8)*N + n] =
                make_float2(acc[m][nb][2] + bb.x, acc[m][nb][3] + bb.y);
        }
    }
}

// ============================================================================
// Causal flash attention: QK^T in fp16-accumulator mma (2x rate; C fragments
// are directly the half2 score pairs -> ex2.f16x2 on accumulators, masking by
// bitwise AND after ex2). PV keeps fp32 accumulators. Register-resident P.
// Grid (32, 16), largest Q tile first.
// ============================================================================
#define STH 72   // halves; rows 144B apart -> LDSM conflict-free
#define SMEM_ATT ((128*STH + 2*64*STH + 2*64*STH) * (int)sizeof(__half))

__global__ __launch_bounds__(256, 2) void attn_mma_kernel()
{
    extern __shared__ __half smh[];
    __half* Ps  = smh;                   // 128 x STH (Q staging only)
    __half* Ks0 = Ps + 128*STH;
    __half* Vs0 = Ks0 + 2*64*STH;        // [d][j]

    const int tid  = threadIdx.x;
    const int w    = tid >> 5;
    const int lane = tid & 31;
    const int g    = lane >> 2;
    const int t    = lane & 3;
    const int bh   = blockIdx.y;
    const int it   = (int)gridDim.x - 1 - (int)blockIdx.x;

    const __half* qb = g_q  + (size_t)bh*S_*D_ + (size_t)it*128*D_;
    const __half* kb = g_k  + (size_t)bh*S_*D_;
    const __half* vb = g_vT + (size_t)bh*D_*S_;

    const uint32_t psm = (uint32_t)__cvta_generic_to_shared(Ps);
    const uint32_t ksm = (uint32_t)__cvta_generic_to_shared(Ks0);
    const uint32_t vsm = (uint32_t)__cvta_generic_to_shared(Vs0);

    const int qq = lane >> 3;
    const int rr = lane & 7;
    const int b_off = (((qq >> 1)*8 + rr)*STH + (qq & 1)*8) * 2;
    const int a_off = ((w*16 + (qq & 1)*8 + rr)*STH + (qq >> 1)*8) * 2;

    const int klr = tid >> 2;
    const int klc = (tid & 3) * 16;

    {
        const __half* kr = kb + (size_t)klr*D_ + klc;
        const __half* vr = vb + (size_t)klr*S_ + klc;
        cp16h(&Ks0[klr*STH + klc],     kr);
        cp16h(&Ks0[klr*STH + klc + 8], kr + 8);
        cp16h(&Vs0[klr*STH + klc],     vr);
        cp16h(&Vs0[klr*STH + klc + 8], vr + 8);
        asm volatile("cp.async.commit_group;\n");
    }

    {
        int lr = tid >> 1, lc = (tid & 1)*32;
        #pragma unroll
        for (int i = 0; i < 4; i++)
            *(float4*)&Ps[lr*STH + lc + i*8] = *(const float4*)&qb[lr*D_ + lc + i*8];
    }
    __syncthreads();

    const int row_a = w*16 + g;
    const int row_b = row_a + 8;
    const int gi_a  = it*128 + row_a;
    const int gi_b  = it*128 + row_b;

    uint32_t qf[4][4];
    #pragma unroll
    for (int kc = 0; kc < 4; kc++)
        ldsm_x4(qf[kc][0], qf[kc][1], qf[kc][2], qf[kc][3],
                psm + kc*32 + a_off);

    float oc[8][4];
    #pragma unroll
    for (int nb = 0; nb < 8; nb++)
        #pragma unroll
        for (int r = 0; r < 4; r++) oc[nb][r] = 0.f;
    float l_a = 0.f, l_b = 0.f;

    const int njt = 2*it + 2;

    for (int jt = 0; jt < njt; jt++) {
        const int buf = jt & 1;
        asm volatile("cp.async.wait_group 0;\n");
        __syncthreads();

        if (jt + 1 < njt) {
            const __half* kr = kb + (size_t)((jt+1)*64 + klr)*D_ + klc;
            const __half* vr = vb + (size_t)klr*S_ + (jt+1)*64 + klc;
            __half* Kd = Ks0 + (buf^1)*64*STH;
            __half* Vd = Vs0 + (buf^1)*64*STH;
            cp16h(&Kd[klr*STH + klc],     kr);
            cp16h(&Kd[klr*STH + klc + 8], kr + 8);
            cp16h(&Vd[klr*STH + klc],     vr);
            cp16h(&Vd[klr*STH + klc + 8], vr + 8);
            asm volatile("cp.async.commit_group;\n");
        }

        const uint32_t kbase = ksm + buf*(64*STH*2) + b_off;
        const uint32_t vbase = vsm + buf*(64*STH*2) + b_off;

        // ---- S = Q K^T  (fp16 accumulators: sch[nb][0]={s0,s1}@row_a,
        //                  sch[nb][1]={s2,s3}@row_b, packed half2) ----
        uint32_t sch[8][2];
        #pragma unroll
        for (int nb = 0; nb < 8; nb++) { sch[nb][0] = 0u; sch[nb][1] = 0u; }

        #pragma unroll
        for (int kc = 0; kc < 4; kc++) {
            #pragma unroll
            for (int nbp = 0; nbp < 4; nbp++) {
                uint32_t b0, b1, c0, c1;
                ldsm_x4(b0, b1, c0, c1, kbase + nbp*(16*STH*2) + kc*32);
                mma_f16h(sch[2*nbp][0], sch[2*nbp][1],
                         qf[kc][0], qf[kc][1], qf[kc][2], qf[kc][3], b0, b1);
                mma_f16h(sch[2*nbp+1][0], sch[2*nbp+1][1],
                         qf[kc][0], qf[kc][1], qf[kc][2], qf[kc][3], c0, c1);
            }
        }

        // ---- softmax numerator: ex2.f16x2 directly on accumulators ----
        uint32_t ph0[8], ph1[8];
        #pragma unroll
        for (int nb = 0; nb < 8; nb++) {
            ph0[nb] = h2ex2(sch[nb][0]);
            ph1[nb] = h2ex2(sch[nb][1]);
        }

        // ---- causal mask: zero masked p entries (exact) ----
        if (jt >= 2*it) {
            int jbase = jt*64;
            #pragma unroll
            for (int nb = 0; nb < 8; nb++) {
                int j0 = jbase + nb*8 + 2*t;
                uint32_t ma = (j0 <= gi_a ? 0x0000FFFFu : 0u)
                            | (j0 + 1 <= gi_a ? 0xFFFF0000u : 0u);
                uint32_t mb = (j0 <= gi_b ? 0x0000FFFFu : 0u)
                            | (j0 + 1 <= gi_b ? 0xFFFF0000u : 0u);
                ph0[nb] &= ma;
                ph1[nb] &= mb;
            }
        }

        // ---- row sums: hadd2 tree + fp32 quad shuffles ----
        {
            __half2 ha = u2h(ph0[0]);
            __half2 hb = u2h(ph1[0]);
            #pragma unroll
            for (int nb = 1; nb < 8; nb++) {
                ha = __hadd2(ha, u2h(ph0[nb]));
                hb = __hadd2(hb, u2h(ph1[nb]));
            }
            float2 fa = __half22float2(ha);
            float2 fb = __half22float2(hb);
            float suma = fa.x + fa.y;
            float sumb = fb.x + fb.y;
            suma += __shfl_xor_sync(0xffffffffu, suma, 1);
            suma += __shfl_xor_sync(0xffffffffu, suma, 2);
            sumb += __shfl_xor_sync(0xffffffffu, sumb, 1);
            sumb += __shfl_xor_sync(0xffffffffu, sumb, 2);
            l_a += suma;
            l_b += sumb;
        }

        // ---- O += P V  (fp32 accumulators; A fragments = ph0/ph1) ----
        #pragma unroll
        for (int kc = 0; kc < 4; kc++) {
            uint32_t a0 = ph0[2*kc], a1 = ph1[2*kc];
            uint32_t a2 = ph0[2*kc+1], a3 = ph1[2*kc+1];
            #pragma unroll
            for (int nbp = 0; nbp < 4; nbp++) {
                uint32_t b0, b1, c0, c1;
                ldsm_x4(b0, b1, c0, c1, vbase + nbp*(16*STH*2) + kc*32);
                mma_f16(oc[2*nbp][0], oc[2*nbp][1], oc[2*nbp][2], oc[2*nbp][3],
                        a0, a1, a2, a3, b0, b1);
                mma_f16(oc[2*nbp+1][0], oc[2*nbp+1][1], oc[2*nbp+1][2], oc[2*nbp+1][3],
                        a0, a1, a2, a3, c0, c1);
            }
        }
    }

    {
        float inva = 1.f / l_a, invb = 1.f / l_b;
        int b = bh >> 3, h = bh & 7;
        __half* da = g_att + (size_t)(b*S_ + gi_a)*DM_ + h*D_;
        __half* db = g_att + (size_t)(b*S_ + gi_b)*DM_ + h*D_;
        #pragma unroll
        for (int nb = 0; nb < 8; nb++) {
            *(__half2*)&da[nb*8 + 2*t] =
                __floats2half2_rn(oc[nb][0]*inva, oc[nb][1]*inva);
            *(__half2*)&db[nb*8 + 2*t] =
                __floats2half2_rn(oc[nb][2]*invb, oc[nb][3]*invb);
        }
    }
}

// ============================================================================
extern "C" void kernel_launch(void* const* d_in, const int* in_sizes, int n_in,
                              void* d_out, int out_size)
{
    const float* x  = (const float*)d_in[0];
    const float* Wq = (const float*)d_in[2];
    const float* bq = (const float*)d_in[3];
    const float* Wk = (const float*)d_in[4];
    const float* bk = (const float*)d_in[5];
    const float* Wv = (const float*)d_in[6];
    const float* bv = (const float*)d_in[7];
    const float* Wo = (const float*)d_in[8];
    const float* bo = (const float*)d_in[9];
    float* out = (float*)d_out;

    __half *wo, *att;
    cudaGetSymbolAddress((void**)&wo,  g_wo);
    cudaGetSymbolAddress((void**)&att, g_att);

    prep_kernel<<<5632, 256>>>(x, Wq, Wk, Wv, Wo);

    cudaFuncSetAttribute(qkv_rope_kernel,
                         cudaFuncAttributeMaxDynamicSharedMemorySize, SMEM_GEMM);
    qkv_rope_kernel<<<dim3(12, ROWS_/128), 256, SMEM_GEMM>>>(bq, bk, bv);

    cudaFuncSetAttribute(attn_mma_kernel,
                         cudaFuncAttributeMaxDynamicSharedMemorySize, SMEM_ATT);
    attn_mma_kernel<<<dim3(S_/128, B_*H_), 256, SMEM_ATT>>>();

    cudaFuncSetAttribute(gemm_f16_kernel,
                         cudaFuncAttributeMaxDynamicSharedMemorySize, SMEM_GEMM);
    gemm_f16_kernel<<<dim3(DM_/128, ROWS_/128), 256, SMEM_GEMM>>>(
        att, wo, bo, out, ROWS_, DM_, DM_);
}